// round 7
// baseline (speedup 1.0000x reference)
#include <cuda_runtime.h>
#include <cstdint>

#define NP   100000
#define RREL 3
#define NE   1600000
#define EPC  500000
#define FIN  128
#define FH   64
#define NDST (RREL * NP)          // 300000 scanned rows
#define SCAN_BLK 512
#define SCAN_NB  ((NDST + SCAN_BLK - 1) / SCAN_BLK)   // 586

// ---------------- device scratch (static, allocation-free) ----------------
__device__ int   g_cnt[6 * NP];          // [0:3N) src counts, [3N:6N) dst counts
__device__ float g_rs [6 * NP];          // rsqrt(max(count,1)) same layout
__device__ float g_h  [RREL * NP * FH];  // per-relation projected features (reused for layer 2)
__device__ float g_h1 [NP * FH];         // relu(hetero_conv1)
__device__ int   g_rowptr[NDST + 1];     // CSR row pointers (relations concatenated)
__device__ int   g_cursor[NDST];         // fill cursors
__device__ int   g_csr[RREL * NE];       // src node per in-edge, grouped by (rel,dst)
__device__ int   g_bsum[SCAN_NB];        // scan spine

// Threefry-2x32, 20 rounds, key = (0, 42)  (jax.random.key(42))
__device__ __forceinline__ void threefry_0_42(uint32_t x0, uint32_t x1,
                                              uint32_t& o0, uint32_t& o1) {
    const uint32_t k0 = 0u, k1 = 42u, k2 = 0x1BD11BDAu ^ 0u ^ 42u;
    x0 += k0; x1 += k1;
#define TF_RND(Rv) { x0 += x1; x1 = __funnelshift_l(x1, x1, (Rv)); x1 ^= x0; }
    TF_RND(13) TF_RND(15) TF_RND(26) TF_RND(6)   x0 += k1; x1 += k2 + 1u;
    TF_RND(17) TF_RND(29) TF_RND(16) TF_RND(24)  x0 += k2; x1 += k0 + 2u;
    TF_RND(13) TF_RND(15) TF_RND(26) TF_RND(6)   x0 += k0; x1 += k1 + 3u;
    TF_RND(17) TF_RND(29) TF_RND(16) TF_RND(24)  x0 += k1; x1 += k2 + 4u;
    TF_RND(13) TF_RND(15) TF_RND(26) TF_RND(6)   x0 += k2; x1 += k0 + 5u;
#undef TF_RND
    o0 = x0; o1 = x1;
}

// bits -> jax-style standard normal (uniform in [lo,1) then sqrt(2)*erfinv)
__device__ __forceinline__ float jax_normal(uint32_t bits) {
    const float LO = -0.99999994f;
    float f = __uint_as_float((bits >> 9) | 0x3f800000u) - 1.0f;
    float u = fmaxf(f * 2.0f + LO, LO);
    return 1.41421356237309515f * erfinvf(u);
}

// ---------------- setup kernels ----------------
__global__ void zero_kernel() {
    int i = blockIdx.x * 256 + threadIdx.x;
    if (i < 6 * NP) g_cnt[i] = 0;
}

__global__ void deg_kernel(const int* __restrict__ es, const int* __restrict__ ed) {
    int i = blockIdx.x * 256 + threadIdx.x;
    if (i >= RREL * NE) return;
    int r = i / NE;
    atomicAdd(&g_cnt[r * NP + es[i]], 1);
    atomicAdd(&g_cnt[3 * NP + r * NP + ed[i]], 1);
}

// ---- 3-kernel exclusive scan over dst counts (g_cnt[3NP : 6NP)) ----
__global__ void scan_blocksum_kernel() {
    __shared__ int sm[SCAN_BLK];
    int i = blockIdx.x * SCAN_BLK + threadIdx.x;
    int v = (i < NDST) ? g_cnt[3 * NP + i] : 0;
    sm[threadIdx.x] = v;
    __syncthreads();
    for (int off = SCAN_BLK / 2; off > 0; off >>= 1) {
        if (threadIdx.x < off) sm[threadIdx.x] += sm[threadIdx.x + off];
        __syncthreads();
    }
    if (threadIdx.x == 0) g_bsum[blockIdx.x] = sm[0];
}

__global__ void scan_spine_kernel() {   // 1 block of 1024, exclusive scan of SCAN_NB sums
    __shared__ int sm[1024];
    int t = threadIdx.x;
    int v = (t < SCAN_NB) ? g_bsum[t] : 0;
    sm[t] = v;
    __syncthreads();
    for (int off = 1; off < 1024; off <<= 1) {
        int add = (t >= off) ? sm[t - off] : 0;
        __syncthreads();
        sm[t] += add;
        __syncthreads();
    }
    if (t < SCAN_NB) g_bsum[t] = sm[t] - v;   // exclusive
}

// scan apply + rs computation (merged, one less launch)
__global__ void scan_apply_kernel() {
    __shared__ int sm[SCAN_BLK];
    int i = blockIdx.x * SCAN_BLK + threadIdx.x;
    int t = threadIdx.x;
    int v = (i < NDST) ? g_cnt[3 * NP + i] : 0;
    sm[t] = v;
    __syncthreads();
    for (int off = 1; off < SCAN_BLK; off <<= 1) {
        int add = (t >= off) ? sm[t - off] : 0;
        __syncthreads();
        sm[t] += add;
        __syncthreads();
    }
    if (i < NDST) {
        int excl = g_bsum[blockIdx.x] + sm[t] - v;
        g_rowptr[i] = excl;
        g_cursor[i] = excl;
        g_rs[i]          = rsqrtf(fmaxf((float)g_cnt[i], 1.0f));          // src scale
        g_rs[3 * NP + i] = rsqrtf(fmaxf((float)v, 1.0f));                 // dst scale
    }
    if (i == 0) g_rowptr[NDST] = RREL * NE;
}

__global__ void fill_csr_kernel(const int* __restrict__ es, const int* __restrict__ ed) {
    int i = blockIdx.x * 256 + threadIdx.x;
    if (i >= RREL * NE) return;
    int r = i / NE;
    int pos = atomicAdd(&g_cursor[r * NP + ed[i]], 1);
    g_csr[pos] = es[i];
}

// ---------------- layer-1 projection: 256 threads ----------------
__global__ void __launch_bounds__(256) proj1_kernel(const float* __restrict__ x,
                                                    const float* __restrict__ W0) {
    __shared__ float xs[128 * 33];   // 128 rows x 32-k chunk, stride 33
    __shared__ float Ws[32 * 64];    // k-chunk x 64 cols
    const int r = blockIdx.y, t = threadIdx.x, m0 = blockIdx.x * 128;
    const int lane = t & 31, wid = t >> 5;
    const int cg = wid & 3, rg = wid >> 2;       // col-group 0..3, row-group 0..1
    const int c0 = cg * 16;

    float4 acc[2][4];
#pragma unroll
    for (int j = 0; j < 2; ++j)
#pragma unroll
        for (int q = 0; q < 4; ++q) acc[j][q] = make_float4(0.f, 0.f, 0.f, 0.f);

    const float4* x4 = (const float4*)x;
    const float* W = W0 + r * FIN * FH;

    for (int c = 0; c < 4; ++c) {
#pragma unroll
        for (int it = 0; it < 4; ++it) {
            int idx = t + it * 256;
            int row = idx >> 3, q = idx & 7;
            int m = m0 + row;
            float4 v = make_float4(0.f, 0.f, 0.f, 0.f); float s = 0.f;
            if (m < NP) { v = x4[m * 32 + c * 8 + q]; s = g_rs[r * NP + m]; }
            float* p = &xs[row * 33 + q * 4];
            p[0] = v.x * s; p[1] = v.y * s; p[2] = v.z * s; p[3] = v.w * s;
        }
#pragma unroll
        for (int i = t; i < 32 * 64; i += 256) Ws[i] = W[c * 32 * 64 + i];
        __syncthreads();

        for (int k = 0; k < 32; ++k) {
            float4 w0 = *(const float4*)&Ws[k * 64 + c0];
            float4 w1 = *(const float4*)&Ws[k * 64 + c0 + 4];
            float4 w2 = *(const float4*)&Ws[k * 64 + c0 + 8];
            float4 w3 = *(const float4*)&Ws[k * 64 + c0 + 12];
#pragma unroll
            for (int j = 0; j < 2; ++j) {
                float xv = xs[(rg * 64 + j * 32 + lane) * 33 + k];
                acc[j][0].x = fmaf(xv, w0.x, acc[j][0].x);
                acc[j][0].y = fmaf(xv, w0.y, acc[j][0].y);
                acc[j][0].z = fmaf(xv, w0.z, acc[j][0].z);
                acc[j][0].w = fmaf(xv, w0.w, acc[j][0].w);
                acc[j][1].x = fmaf(xv, w1.x, acc[j][1].x);
                acc[j][1].y = fmaf(xv, w1.y, acc[j][1].y);
                acc[j][1].z = fmaf(xv, w1.z, acc[j][1].z);
                acc[j][1].w = fmaf(xv, w1.w, acc[j][1].w);
                acc[j][2].x = fmaf(xv, w2.x, acc[j][2].x);
                acc[j][2].y = fmaf(xv, w2.y, acc[j][2].y);
                acc[j][2].z = fmaf(xv, w2.z, acc[j][2].z);
                acc[j][2].w = fmaf(xv, w2.w, acc[j][2].w);
                acc[j][3].x = fmaf(xv, w3.x, acc[j][3].x);
                acc[j][3].y = fmaf(xv, w3.y, acc[j][3].y);
                acc[j][3].z = fmaf(xv, w3.z, acc[j][3].z);
                acc[j][3].w = fmaf(xv, w3.w, acc[j][3].w);
            }
        }
        __syncthreads();
    }

#pragma unroll
    for (int j = 0; j < 2; ++j) {
        int m = m0 + rg * 64 + j * 32 + lane;
        if (m >= NP) continue;
        float4* o = (float4*)&g_h[(r * NP + m) * FH + c0];
        o[0] = acc[j][0]; o[1] = acc[j][1]; o[2] = acc[j][2]; o[3] = acc[j][3];
    }
}

// ---------------- layer-1 gather: half-warp split, float4 (LDG.128) ----------------
// Warp owns node w. Lanes 0-15 process edges [beg, beg+n0), lanes 16-31 the rest.
// Each lane loads float4 covering dims [4*hl, 4*hl+4) -> one 256B row per LDG.128.
__global__ void __launch_bounds__(256) gather1_kernel(const float* __restrict__ b0) {
    int w = (blockIdx.x * 256 + threadIdx.x) >> 5;   // dst node
    int lane = threadIdx.x & 31;
    int half = lane >> 4, hl = lane & 15;
    if (w >= NP) return;
    float4 a = make_float4(0.f, 0.f, 0.f, 0.f);
#pragma unroll
    for (int r = 0; r < RREL; ++r) {
        int beg = g_rowptr[r * NP + w];
        int end = g_rowptr[r * NP + w + 1];
        int n0  = (end - beg + 1) >> 1;
        int e   = half ? beg + n0 : beg;
        int e1  = half ? end      : beg + n0;
        float sc = g_rs[3 * NP + r * NP + w];
        const float4* h4 = (const float4*)(g_h + (size_t)r * NP * FH);
        float4 s = make_float4(0.f, 0.f, 0.f, 0.f);
        for (; e + 4 <= e1; e += 4) {
            int i0 = g_csr[e], i1 = g_csr[e + 1], i2 = g_csr[e + 2], i3 = g_csr[e + 3];
            float4 v0 = h4[i0 * 16 + hl];
            float4 v1 = h4[i1 * 16 + hl];
            float4 v2 = h4[i2 * 16 + hl];
            float4 v3 = h4[i3 * 16 + hl];
            s.x += (v0.x + v1.x) + (v2.x + v3.x);
            s.y += (v0.y + v1.y) + (v2.y + v3.y);
            s.z += (v0.z + v1.z) + (v2.z + v3.z);
            s.w += (v0.w + v1.w) + (v2.w + v3.w);
        }
        for (; e < e1; ++e) {
            float4 v = h4[g_csr[e] * 16 + hl];
            s.x += v.x; s.y += v.y; s.z += v.z; s.w += v.w;
        }
        a.x = fmaf(sc, s.x, a.x);
        a.y = fmaf(sc, s.y, a.y);
        a.z = fmaf(sc, s.z, a.z);
        a.w = fmaf(sc, s.w, a.w);
    }
    // combine the two halves
    a.x += __shfl_xor_sync(0xffffffffu, a.x, 16);
    a.y += __shfl_xor_sync(0xffffffffu, a.y, 16);
    a.z += __shfl_xor_sync(0xffffffffu, a.z, 16);
    a.w += __shfl_xor_sync(0xffffffffu, a.w, 16);
    if (half == 0) {
        int f = 4 * hl;
        float4 o;
        o.x = fmaxf(a.x + b0[f]     + b0[FH + f]     + b0[2 * FH + f],     0.f);
        o.y = fmaxf(a.y + b0[f + 1] + b0[FH + f + 1] + b0[2 * FH + f + 1], 0.f);
        o.z = fmaxf(a.z + b0[f + 2] + b0[FH + f + 2] + b0[2 * FH + f + 2], 0.f);
        o.w = fmaxf(a.w + b0[f + 3] + b0[FH + f + 3] + b0[2 * FH + f + 3], 0.f);
        *(float4*)&g_h1[w * FH + f] = o;
    }
}

// ---------------- layer-2 projection: 256 threads ----------------
__global__ void __launch_bounds__(256) proj2_kernel(const float* __restrict__ Wmu,
                                                    const float* __restrict__ Wls) {
    __shared__ float xs[128 * 65];
    __shared__ float Ws[64 * 32];
    const int r = blockIdx.y, t = threadIdx.x, m0 = blockIdx.x * 128;
    const int lane = t & 31, wid = t >> 5;
    const int cg = wid & 3, rg = wid >> 2;
    const int c0 = cg * 8;

    for (int i = t; i < 64 * 16; i += 256) {
        int k = i >> 4, c = i & 15;
        Ws[k * 32 + c]      = Wmu[r * 1024 + i];
        Ws[k * 32 + 16 + c] = Wls[r * 1024 + i];
    }
    const float4* h4 = (const float4*)g_h1;
#pragma unroll
    for (int it = 0; it < 8; ++it) {
        int idx = t + it * 256;
        int row = idx >> 4, q = idx & 15;
        int m = m0 + row;
        float4 v = make_float4(0.f, 0.f, 0.f, 0.f); float s = 0.f;
        if (m < NP) { v = h4[m * 16 + q]; s = g_rs[r * NP + m]; }
        float* p = &xs[row * 65 + q * 4];
        p[0] = v.x * s; p[1] = v.y * s; p[2] = v.z * s; p[3] = v.w * s;
    }
    __syncthreads();

    float4 acc[2][2];
#pragma unroll
    for (int j = 0; j < 2; ++j) {
        acc[j][0] = make_float4(0.f, 0.f, 0.f, 0.f);
        acc[j][1] = make_float4(0.f, 0.f, 0.f, 0.f);
    }

    for (int k = 0; k < 64; ++k) {
        float4 w0 = *(const float4*)&Ws[k * 32 + c0];
        float4 w1 = *(const float4*)&Ws[k * 32 + c0 + 4];
#pragma unroll
        for (int j = 0; j < 2; ++j) {
            float xv = xs[(rg * 64 + j * 32 + lane) * 65 + k];
            acc[j][0].x = fmaf(xv, w0.x, acc[j][0].x);
            acc[j][0].y = fmaf(xv, w0.y, acc[j][0].y);
            acc[j][0].z = fmaf(xv, w0.z, acc[j][0].z);
            acc[j][0].w = fmaf(xv, w0.w, acc[j][0].w);
            acc[j][1].x = fmaf(xv, w1.x, acc[j][1].x);
            acc[j][1].y = fmaf(xv, w1.y, acc[j][1].y);
            acc[j][1].z = fmaf(xv, w1.z, acc[j][1].z);
            acc[j][1].w = fmaf(xv, w1.w, acc[j][1].w);
        }
    }
#pragma unroll
    for (int j = 0; j < 2; ++j) {
        int m = m0 + rg * 64 + j * 32 + lane;
        if (m >= NP) continue;
        float4* o = (float4*)&g_h[(r * NP + m) * 32 + c0];
        o[0] = acc[j][0]; o[1] = acc[j][1];
    }
}

// ---------------- layer-2 gather — fuses bias + VGAE reparameterization ----------------
__global__ void __launch_bounds__(256) gather2_kernel(const float* __restrict__ bmu,
                                                      const float* __restrict__ bls,
                                                      float* __restrict__ out) {
    int w = (blockIdx.x * 256 + threadIdx.x) >> 5;   // dst node
    int lane = threadIdx.x & 31;
    if (w >= NP) return;
    float acc = 0.f;
#pragma unroll
    for (int r = 0; r < RREL; ++r) {
        int beg = g_rowptr[r * NP + w];
        int end = g_rowptr[r * NP + w + 1];
        float sc = g_rs[3 * NP + r * NP + w];
        const float* hb = g_h + (size_t)r * NP * 32;
        float s0 = 0.f;
        int e = beg;
        for (; e + 8 <= end; e += 8) {
            int i0 = g_csr[e],     i1 = g_csr[e + 1], i2 = g_csr[e + 2], i3 = g_csr[e + 3];
            int i4 = g_csr[e + 4], i5 = g_csr[e + 5], i6 = g_csr[e + 6], i7 = g_csr[e + 7];
            float v0 = hb[i0 * 32 + lane], v1 = hb[i1 * 32 + lane];
            float v2 = hb[i2 * 32 + lane], v3 = hb[i3 * 32 + lane];
            float v4 = hb[i4 * 32 + lane], v5 = hb[i5 * 32 + lane];
            float v6 = hb[i6 * 32 + lane], v7 = hb[i7 * 32 + lane];
            s0 += ((v0 + v1) + (v2 + v3)) + ((v4 + v5) + (v6 + v7));
        }
        for (; e + 4 <= end; e += 4) {
            int i0 = g_csr[e], i1 = g_csr[e + 1], i2 = g_csr[e + 2], i3 = g_csr[e + 3];
            s0 += (hb[i0 * 32 + lane] + hb[i1 * 32 + lane])
                + (hb[i2 * 32 + lane] + hb[i3 * 32 + lane]);
        }
        for (; e < end; ++e) s0 += hb[g_csr[e] * 32 + lane];
        acc = fmaf(sc, s0, acc);
    }
    // lanes 0..15: mean dims; lanes 16..31: log_std dims
    float bias = (lane < 16)
        ? (bmu[lane] + bmu[16 + lane] + bmu[32 + lane])
        : (bls[lane - 16] + bls[lane] + bls[lane + 16]);
    float val = acc + bias;
    float ls  = __shfl_sync(0xffffffffu, val, (lane + 16) & 31);
    uint32_t o0, o1;
    threefry_0_42(0u, (uint32_t)(w * 16 + lane), o0, o1);
    if (lane < 16)
        out[1000000 + w * 16 + lane] = val + jax_normal(o0 ^ o1) * expf(ls);
}

__global__ void score_kernel(const int* __restrict__ ps, const int* __restrict__ pd,
                             const int* __restrict__ ns, const int* __restrict__ nd,
                             float* __restrict__ out) {
    int i = blockIdx.x * 256 + threadIdx.x;
    if (i >= 2 * EPC) return;
    int s, d;
    if (i < EPC) { s = ps[i]; d = pd[i]; }
    else         { s = ns[i - EPC]; d = nd[i - EPC]; }
    const float4* h4 = (const float4*)(out + 1000000);
    float acc = 0.f;
#pragma unroll
    for (int q = 0; q < 4; ++q) {
        float4 a = h4[s * 4 + q], b = h4[d * 4 + q];
        acc += a.x * b.x + a.y * b.y + a.z * b.z + a.w * b.w;
    }
    out[i] = acc;
}

// ---------------- launch ----------------
extern "C" void kernel_launch(void* const* d_in, const int* in_sizes, int n_in,
                              void* d_out, int out_size) {
    const float* x   = (const float*)d_in[0];
    const float* W0  = (const float*)d_in[1];
    const float* b0  = (const float*)d_in[2];
    const float* Wmu = (const float*)d_in[3];
    const float* bmu = (const float*)d_in[4];
    const float* Wls = (const float*)d_in[5];
    const float* bls = (const float*)d_in[6];
    const int*   es  = (const int*)d_in[7];
    const int*   ed  = (const int*)d_in[8];
    const int*   ps  = (const int*)d_in[9];
    const int*   pd  = (const int*)d_in[10];
    const int*   ns  = (const int*)d_in[11];
    const int*   nd  = (const int*)d_in[12];
    float* out = (float*)d_out;

    const int MBLK = (NP + 127) / 128;            // 782
    const int GBLK = (NP * 32 + 255) / 256;       // warp-per-node grids

    zero_kernel         <<<(6 * NP + 255) / 256, 256>>>();
    deg_kernel          <<<(RREL * NE + 255) / 256, 256>>>(es, ed);
    scan_blocksum_kernel<<<SCAN_NB, SCAN_BLK>>>();
    scan_spine_kernel   <<<1, 1024>>>();
    scan_apply_kernel   <<<SCAN_NB, SCAN_BLK>>>();
    fill_csr_kernel     <<<(RREL * NE + 255) / 256, 256>>>(es, ed);
    proj1_kernel        <<<dim3(MBLK, RREL), 256>>>(x, W0);
    gather1_kernel      <<<GBLK, 256>>>(b0);
    proj2_kernel        <<<dim3(MBLK, RREL), 256>>>(Wmu, Wls);
    gather2_kernel      <<<GBLK, 256>>>(bmu, bls, out);
    score_kernel        <<<(2 * EPC + 255) / 256, 256>>>(ps, pd, ns, nd, out);
}

// round 9
// speedup vs baseline: 1.0078x; 1.0078x over previous
#include <cuda_runtime.h>
#include <cstdint>

#define NP   100000
#define RREL 3
#define NE   1600000
#define EPC  500000
#define FIN  128
#define FH   64
#define NDST (RREL * NP)          // 300000 scanned rows
#define SCAN_BLK 512
#define SCAN_NB  ((NDST + SCAN_BLK - 1) / SCAN_BLK)   // 586
#define MBLK 782                  // ceil(NP/128)
#define PROJB (RREL * MBLK)       // 2346 proj1 blocks
#define FUSED_GRID (PROJB * 9)    // 1:8 interleave proj:fill

// ---------------- device scratch (static, allocation-free) ----------------
__device__ int   g_cnt[6 * NP];          // [0:3N) src counts, [3N:6N) dst counts
__device__ float g_rs [6 * NP];          // rsqrt(max(count,1)) same layout
__device__ float g_h  [RREL * NP * FH];  // per-relation projected features (reused for layer 2)
__device__ float g_h1 [NP * FH];         // relu(hetero_conv1)
__device__ int   g_rowptr[NDST + 1];     // CSR row pointers (relations concatenated)
__device__ int   g_cursor[NDST];         // fill cursors
__device__ int   g_csr[RREL * NE];       // src node per in-edge, grouped by (rel,dst)
__device__ int   g_bsum[SCAN_NB];        // scan spine

// Threefry-2x32, 20 rounds, key = (0, 42)  (jax.random.key(42))
__device__ __forceinline__ void threefry_0_42(uint32_t x0, uint32_t x1,
                                              uint32_t& o0, uint32_t& o1) {
    const uint32_t k0 = 0u, k1 = 42u, k2 = 0x1BD11BDAu ^ 0u ^ 42u;
    x0 += k0; x1 += k1;
#define TF_RND(Rv) { x0 += x1; x1 = __funnelshift_l(x1, x1, (Rv)); x1 ^= x0; }
    TF_RND(13) TF_RND(15) TF_RND(26) TF_RND(6)   x0 += k1; x1 += k2 + 1u;
    TF_RND(17) TF_RND(29) TF_RND(16) TF_RND(24)  x0 += k2; x1 += k0 + 2u;
    TF_RND(13) TF_RND(15) TF_RND(26) TF_RND(6)   x0 += k0; x1 += k1 + 3u;
    TF_RND(17) TF_RND(29) TF_RND(16) TF_RND(24)  x0 += k1; x1 += k2 + 4u;
    TF_RND(13) TF_RND(15) TF_RND(26) TF_RND(6)   x0 += k2; x1 += k0 + 5u;
#undef TF_RND
    o0 = x0; o1 = x1;
}

// bits -> jax-style standard normal (uniform in [lo,1) then sqrt(2)*erfinv)
__device__ __forceinline__ float jax_normal(uint32_t bits) {
    const float LO = -0.99999994f;
    float f = __uint_as_float((bits >> 9) | 0x3f800000u) - 1.0f;
    float u = fmaxf(f * 2.0f + LO, LO);
    return 1.41421356237309515f * erfinvf(u);
}

// ---------------- setup kernels ----------------
__global__ void zero_kernel() {
    int i = blockIdx.x * 256 + threadIdx.x;
    if (i < 6 * NP) g_cnt[i] = 0;
}

__global__ void deg_kernel(const int* __restrict__ es, const int* __restrict__ ed) {
    int i = blockIdx.x * 256 + threadIdx.x;
    if (i >= RREL * NE) return;
    int r = i / NE;
    atomicAdd(&g_cnt[r * NP + es[i]], 1);
    atomicAdd(&g_cnt[3 * NP + r * NP + ed[i]], 1);
}

// ---- 3-kernel exclusive scan over dst counts (g_cnt[3NP : 6NP)) ----
__global__ void scan_blocksum_kernel() {
    __shared__ int sm[SCAN_BLK];
    int i = blockIdx.x * SCAN_BLK + threadIdx.x;
    int v = (i < NDST) ? g_cnt[3 * NP + i] : 0;
    sm[threadIdx.x] = v;
    __syncthreads();
    for (int off = SCAN_BLK / 2; off > 0; off >>= 1) {
        if (threadIdx.x < off) sm[threadIdx.x] += sm[threadIdx.x + off];
        __syncthreads();
    }
    if (threadIdx.x == 0) g_bsum[blockIdx.x] = sm[0];
}

__global__ void scan_spine_kernel() {   // 1 block of 1024, exclusive scan of SCAN_NB sums
    __shared__ int sm[1024];
    int t = threadIdx.x;
    int v = (t < SCAN_NB) ? g_bsum[t] : 0;
    sm[t] = v;
    __syncthreads();
    for (int off = 1; off < 1024; off <<= 1) {
        int add = (t >= off) ? sm[t - off] : 0;
        __syncthreads();
        sm[t] += add;
        __syncthreads();
    }
    if (t < SCAN_NB) g_bsum[t] = sm[t] - v;   // exclusive
}

// scan apply + rs computation (merged)
__global__ void scan_apply_kernel() {
    __shared__ int sm[SCAN_BLK];
    int i = blockIdx.x * SCAN_BLK + threadIdx.x;
    int t = threadIdx.x;
    int v = (i < NDST) ? g_cnt[3 * NP + i] : 0;
    sm[t] = v;
    __syncthreads();
    for (int off = 1; off < SCAN_BLK; off <<= 1) {
        int add = (t >= off) ? sm[t - off] : 0;
        __syncthreads();
        sm[t] += add;
        __syncthreads();
    }
    if (i < NDST) {
        int excl = g_bsum[blockIdx.x] + sm[t] - v;
        g_rowptr[i] = excl;
        g_cursor[i] = excl;
        g_rs[i]          = rsqrtf(fmaxf((float)g_cnt[i], 1.0f));          // src scale
        g_rs[3 * NP + i] = rsqrtf(fmaxf((float)v, 1.0f));                 // dst scale
    }
    if (i == 0) g_rowptr[NDST] = RREL * NE;
}

// ---------------- FUSED: layer-1 projection + CSR fill ----------------
// Every 9th block is a proj1 tile (2346 of them); the rest run fill_csr slices
// (18768 slices cover 4.8M edges). Both depend only on scan_apply outputs, so
// they are independent; interleaving overlaps FMA-bound proj with atomic-bound fill.
__global__ void __launch_bounds__(256) proj1_fill_kernel(const float* __restrict__ x,
                                                         const float* __restrict__ W0,
                                                         const int* __restrict__ es,
                                                         const int* __restrict__ ed) {
    const int bid = blockIdx.x;
    const int t = threadIdx.x;

    if (bid % 9 != 0) {
        // ---- fill_csr slice ----
        int fb = bid - bid / 9 - 1;              // 0 .. 18767
        int i = fb * 256 + t;
        if (i < RREL * NE) {
            int r = i / NE;
            int pos = atomicAdd(&g_cursor[r * NP + ed[i]], 1);
            g_csr[pos] = es[i];
        }
        return;
    }

    // ---- proj1 tile ----
    __shared__ float xs[128 * 33];   // 128 rows x 32-k chunk, stride 33
    __shared__ float Ws[32 * 64];    // k-chunk x 64 cols
    const int pb = bid / 9;                       // 0 .. PROJB-1
    const int r = pb / MBLK, m0 = (pb % MBLK) * 128;
    const int lane = t & 31, wid = t >> 5;
    const int cg = wid & 3, rg = wid >> 2;        // col-group 0..3, row-group 0..1
    const int c0 = cg * 16;

    float4 acc[2][4];
#pragma unroll
    for (int j = 0; j < 2; ++j)
#pragma unroll
        for (int q = 0; q < 4; ++q) acc[j][q] = make_float4(0.f, 0.f, 0.f, 0.f);

    const float4* x4 = (const float4*)x;
    const float* W = W0 + r * FIN * FH;

    for (int c = 0; c < 4; ++c) {
#pragma unroll
        for (int it = 0; it < 4; ++it) {
            int idx = t + it * 256;
            int row = idx >> 3, q = idx & 7;
            int m = m0 + row;
            float4 v = make_float4(0.f, 0.f, 0.f, 0.f); float s = 0.f;
            if (m < NP) { v = x4[m * 32 + c * 8 + q]; s = g_rs[r * NP + m]; }
            float* p = &xs[row * 33 + q * 4];
            p[0] = v.x * s; p[1] = v.y * s; p[2] = v.z * s; p[3] = v.w * s;
        }
#pragma unroll
        for (int i = t; i < 32 * 64; i += 256) Ws[i] = W[c * 32 * 64 + i];
        __syncthreads();

        for (int k = 0; k < 32; ++k) {
            float4 w0 = *(const float4*)&Ws[k * 64 + c0];
            float4 w1 = *(const float4*)&Ws[k * 64 + c0 + 4];
            float4 w2 = *(const float4*)&Ws[k * 64 + c0 + 8];
            float4 w3 = *(const float4*)&Ws[k * 64 + c0 + 12];
#pragma unroll
            for (int j = 0; j < 2; ++j) {
                float xv = xs[(rg * 64 + j * 32 + lane) * 33 + k];
                acc[j][0].x = fmaf(xv, w0.x, acc[j][0].x);
                acc[j][0].y = fmaf(xv, w0.y, acc[j][0].y);
                acc[j][0].z = fmaf(xv, w0.z, acc[j][0].z);
                acc[j][0].w = fmaf(xv, w0.w, acc[j][0].w);
                acc[j][1].x = fmaf(xv, w1.x, acc[j][1].x);
                acc[j][1].y = fmaf(xv, w1.y, acc[j][1].y);
                acc[j][1].z = fmaf(xv, w1.z, acc[j][1].z);
                acc[j][1].w = fmaf(xv, w1.w, acc[j][1].w);
                acc[j][2].x = fmaf(xv, w2.x, acc[j][2].x);
                acc[j][2].y = fmaf(xv, w2.y, acc[j][2].y);
                acc[j][2].z = fmaf(xv, w2.z, acc[j][2].z);
                acc[j][2].w = fmaf(xv, w2.w, acc[j][2].w);
                acc[j][3].x = fmaf(xv, w3.x, acc[j][3].x);
                acc[j][3].y = fmaf(xv, w3.y, acc[j][3].y);
                acc[j][3].z = fmaf(xv, w3.z, acc[j][3].z);
                acc[j][3].w = fmaf(xv, w3.w, acc[j][3].w);
            }
        }
        __syncthreads();
    }

#pragma unroll
    for (int j = 0; j < 2; ++j) {
        int m = m0 + rg * 64 + j * 32 + lane;
        if (m >= NP) continue;
        float4* o = (float4*)&g_h[(r * NP + m) * FH + c0];
        o[0] = acc[j][0]; o[1] = acc[j][1]; o[2] = acc[j][2]; o[3] = acc[j][3];
    }
}

// ---------------- layer-1 gather (pull, CSR) — 4-edge unroll (R5 best config) ----------------
__global__ void __launch_bounds__(256) gather1_kernel(const float* __restrict__ b0) {
    int w = (blockIdx.x * 256 + threadIdx.x) >> 5;   // dst node
    int lane = threadIdx.x & 31;
    if (w >= NP) return;
    float a0 = 0.f, a1 = 0.f;
#pragma unroll
    for (int r = 0; r < RREL; ++r) {
        int beg = g_rowptr[r * NP + w];
        int end = g_rowptr[r * NP + w + 1];
        float sc = g_rs[3 * NP + r * NP + w];
        const float* hb = g_h + (size_t)r * NP * FH;
        float s0 = 0.f, s1 = 0.f;
        int e = beg;
        for (; e + 4 <= end; e += 4) {
            int i0 = g_csr[e], i1 = g_csr[e + 1], i2 = g_csr[e + 2], i3 = g_csr[e + 3];
            float v0a = hb[i0 * FH + lane], v0b = hb[i0 * FH + 32 + lane];
            float v1a = hb[i1 * FH + lane], v1b = hb[i1 * FH + 32 + lane];
            float v2a = hb[i2 * FH + lane], v2b = hb[i2 * FH + 32 + lane];
            float v3a = hb[i3 * FH + lane], v3b = hb[i3 * FH + 32 + lane];
            s0 += (v0a + v1a) + (v2a + v3a);
            s1 += (v0b + v1b) + (v2b + v3b);
        }
        for (; e < end; ++e) {
            int s = g_csr[e];
            s0 += hb[s * FH + lane];
            s1 += hb[s * FH + 32 + lane];
        }
        a0 = fmaf(sc, s0, a0);
        a1 = fmaf(sc, s1, a1);
    }
    float bs0 = b0[lane]      + b0[FH + lane]      + b0[2 * FH + lane];
    float bs1 = b0[32 + lane] + b0[FH + 32 + lane] + b0[2 * FH + 32 + lane];
    g_h1[w * FH + lane]      = fmaxf(a0 + bs0, 0.f);
    g_h1[w * FH + 32 + lane] = fmaxf(a1 + bs1, 0.f);
}

// ---------------- layer-2 projection: 256 threads ----------------
__global__ void __launch_bounds__(256) proj2_kernel(const float* __restrict__ Wmu,
                                                    const float* __restrict__ Wls) {
    __shared__ float xs[128 * 65];
    __shared__ float Ws[64 * 32];
    const int r = blockIdx.y, t = threadIdx.x, m0 = blockIdx.x * 128;
    const int lane = t & 31, wid = t >> 5;
    const int cg = wid & 3, rg = wid >> 2;
    const int c0 = cg * 8;

    for (int i = t; i < 64 * 16; i += 256) {
        int k = i >> 4, c = i & 15;
        Ws[k * 32 + c]      = Wmu[r * 1024 + i];
        Ws[k * 32 + 16 + c] = Wls[r * 1024 + i];
    }
    const float4* h4 = (const float4*)g_h1;
#pragma unroll
    for (int it = 0; it < 8; ++it) {
        int idx = t + it * 256;
        int row = idx >> 4, q = idx & 15;
        int m = m0 + row;
        float4 v = make_float4(0.f, 0.f, 0.f, 0.f); float s = 0.f;
        if (m < NP) { v = h4[m * 16 + q]; s = g_rs[r * NP + m]; }
        float* p = &xs[row * 65 + q * 4];
        p[0] = v.x * s; p[1] = v.y * s; p[2] = v.z * s; p[3] = v.w * s;
    }
    __syncthreads();

    float4 acc[2][2];
#pragma unroll
    for (int j = 0; j < 2; ++j) {
        acc[j][0] = make_float4(0.f, 0.f, 0.f, 0.f);
        acc[j][1] = make_float4(0.f, 0.f, 0.f, 0.f);
    }

    for (int k = 0; k < 64; ++k) {
        float4 w0 = *(const float4*)&Ws[k * 32 + c0];
        float4 w1 = *(const float4*)&Ws[k * 32 + c0 + 4];
#pragma unroll
        for (int j = 0; j < 2; ++j) {
            float xv = xs[(rg * 64 + j * 32 + lane) * 65 + k];
            acc[j][0].x = fmaf(xv, w0.x, acc[j][0].x);
            acc[j][0].y = fmaf(xv, w0.y, acc[j][0].y);
            acc[j][0].z = fmaf(xv, w0.z, acc[j][0].z);
            acc[j][0].w = fmaf(xv, w0.w, acc[j][0].w);
            acc[j][1].x = fmaf(xv, w1.x, acc[j][1].x);
            acc[j][1].y = fmaf(xv, w1.y, acc[j][1].y);
            acc[j][1].z = fmaf(xv, w1.z, acc[j][1].z);
            acc[j][1].w = fmaf(xv, w1.w, acc[j][1].w);
        }
    }
#pragma unroll
    for (int j = 0; j < 2; ++j) {
        int m = m0 + rg * 64 + j * 32 + lane;
        if (m >= NP) continue;
        float4* o = (float4*)&g_h[(r * NP + m) * 32 + c0];
        o[0] = acc[j][0]; o[1] = acc[j][1];
    }
}

// ---------------- layer-2 gather — fuses bias + VGAE reparameterization ----------------
__global__ void __launch_bounds__(256) gather2_kernel(const float* __restrict__ bmu,
                                                      const float* __restrict__ bls,
                                                      float* __restrict__ out) {
    int w = (blockIdx.x * 256 + threadIdx.x) >> 5;   // dst node
    int lane = threadIdx.x & 31;
    if (w >= NP) return;
    float acc = 0.f;
#pragma unroll
    for (int r = 0; r < RREL; ++r) {
        int beg = g_rowptr[r * NP + w];
        int end = g_rowptr[r * NP + w + 1];
        float sc = g_rs[3 * NP + r * NP + w];
        const float* hb = g_h + (size_t)r * NP * 32;
        float s0 = 0.f;
        int e = beg;
        for (; e + 4 <= end; e += 4) {
            int i0 = g_csr[e], i1 = g_csr[e + 1], i2 = g_csr[e + 2], i3 = g_csr[e + 3];
            s0 += (hb[i0 * 32 + lane] + hb[i1 * 32 + lane])
                + (hb[i2 * 32 + lane] + hb[i3 * 32 + lane]);
        }
        for (; e < end; ++e) s0 += hb[g_csr[e] * 32 + lane];
        acc = fmaf(sc, s0, acc);
    }
    // lanes 0..15: mean dims; lanes 16..31: log_std dims
    float bias = (lane < 16)
        ? (bmu[lane] + bmu[16 + lane] + bmu[32 + lane])
        : (bls[lane - 16] + bls[lane] + bls[lane + 16]);
    float val = acc + bias;
    float ls  = __shfl_sync(0xffffffffu, val, (lane + 16) & 31);
    uint32_t o0, o1;
    threefry_0_42(0u, (uint32_t)(w * 16 + lane), o0, o1);
    if (lane < 16)
        out[1000000 + w * 16 + lane] = val + jax_normal(o0 ^ o1) * expf(ls);
}

__global__ void score_kernel(const int* __restrict__ ps, const int* __restrict__ pd,
                             const int* __restrict__ ns, const int* __restrict__ nd,
                             float* __restrict__ out) {
    int i = blockIdx.x * 256 + threadIdx.x;
    if (i >= 2 * EPC) return;
    int s, d;
    if (i < EPC) { s = ps[i]; d = pd[i]; }
    else         { s = ns[i - EPC]; d = nd[i - EPC]; }
    const float4* h4 = (const float4*)(out + 1000000);
    float acc = 0.f;
#pragma unroll
    for (int q = 0; q < 4; ++q) {
        float4 a = h4[s * 4 + q], b = h4[d * 4 + q];
        acc += a.x * b.x + a.y * b.y + a.z * b.z + a.w * b.w;
    }
    out[i] = acc;
}

// ---------------- launch ----------------
extern "C" void kernel_launch(void* const* d_in, const int* in_sizes, int n_in,
                              void* d_out, int out_size) {
    const float* x   = (const float*)d_in[0];
    const float* W0  = (const float*)d_in[1];
    const float* b0  = (const float*)d_in[2];
    const float* Wmu = (const float*)d_in[3];
    const float* bmu = (const float*)d_in[4];
    const float* Wls = (const float*)d_in[5];
    const float* bls = (const float*)d_in[6];
    const int*   es  = (const int*)d_in[7];
    const int*   ed  = (const int*)d_in[8];
    const int*   ps  = (const int*)d_in[9];
    const int*   pd  = (const int*)d_in[10];
    const int*   ns  = (const int*)d_in[11];
    const int*   nd  = (const int*)d_in[12];
    float* out = (float*)d_out;

    const int GBLK = (NP * 32 + 255) / 256;       // warp-per-node grids

    zero_kernel         <<<(6 * NP + 255) / 256, 256>>>();
    deg_kernel          <<<(RREL * NE + 255) / 256, 256>>>(es, ed);
    scan_blocksum_kernel<<<SCAN_NB, SCAN_BLK>>>();
    scan_spine_kernel   <<<1, 1024>>>();
    scan_apply_kernel   <<<SCAN_NB, SCAN_BLK>>>();
    proj1_fill_kernel   <<<FUSED_GRID, 256>>>(x, W0, es, ed);
    gather1_kernel      <<<GBLK, 256>>>(b0);
    proj2_kernel        <<<dim3(MBLK, RREL), 256>>>(Wmu, Wls);
    gather2_kernel      <<<GBLK, 256>>>(bmu, bls, out);
    score_kernel        <<<(2 * EPC + 255) / 256, 256>>>(ps, pd, ns, nd, out);
}

// round 10
// speedup vs baseline: 1.1840x; 1.1748x over previous
#include <cuda_runtime.h>
#include <cstdint>

#define NP   100000
#define RREL 3
#define NE   1600000
#define EPC  500000
#define FIN  128
#define FH   64
#define NDST (RREL * NP)          // 300000 scanned rows
#define SCAN_BLK 512
#define SCAN_NB  ((NDST + SCAN_BLK - 1) / SCAN_BLK)   // 586
#define MBLK 782                  // ceil(NP/128)

// ---------------- device scratch (static, allocation-free) ----------------
__device__ int   g_cnt[6 * NP];          // [0:3N) src counts, [3N:6N) dst counts
__device__ float g_rs [6 * NP];          // rsqrt(max(count,1)) same layout
__device__ float g_h  [RREL * NP * FH];  // per-relation projected features (reused for layer 2)
__device__ float g_h1 [NP * FH];         // relu(hetero_conv1)
__device__ int   g_rowptr[NDST + 1];     // CSR row pointers (relations concatenated)
__device__ int   g_cursor[NDST];         // fill cursors
__device__ int   g_csr[RREL * NE];       // src node per in-edge, grouped by (rel,dst)
__device__ int   g_bsum[SCAN_NB];        // scan spine

// Threefry-2x32, 20 rounds, key = (0, 42)  (jax.random.key(42))
__device__ __forceinline__ void threefry_0_42(uint32_t x0, uint32_t x1,
                                              uint32_t& o0, uint32_t& o1) {
    const uint32_t k0 = 0u, k1 = 42u, k2 = 0x1BD11BDAu ^ 0u ^ 42u;
    x0 += k0; x1 += k1;
#define TF_RND(Rv) { x0 += x1; x1 = __funnelshift_l(x1, x1, (Rv)); x1 ^= x0; }
    TF_RND(13) TF_RND(15) TF_RND(26) TF_RND(6)   x0 += k1; x1 += k2 + 1u;
    TF_RND(17) TF_RND(29) TF_RND(16) TF_RND(24)  x0 += k2; x1 += k0 + 2u;
    TF_RND(13) TF_RND(15) TF_RND(26) TF_RND(6)   x0 += k0; x1 += k1 + 3u;
    TF_RND(17) TF_RND(29) TF_RND(16) TF_RND(24)  x0 += k1; x1 += k2 + 4u;
    TF_RND(13) TF_RND(15) TF_RND(26) TF_RND(6)   x0 += k2; x1 += k0 + 5u;
#undef TF_RND
    o0 = x0; o1 = x1;
}

// bits -> jax-style standard normal (uniform in [lo,1) then sqrt(2)*erfinv)
__device__ __forceinline__ float jax_normal(uint32_t bits) {
    const float LO = -0.99999994f;
    float f = __uint_as_float((bits >> 9) | 0x3f800000u) - 1.0f;
    float u = fmaxf(f * 2.0f + LO, LO);
    return 1.41421356237309515f * erfinvf(u);
}

__device__ __forceinline__ uint32_t f2tf32(float f) {
    uint32_t r;
    asm("cvt.rna.tf32.f32 %0, %1;" : "=r"(r) : "f"(f));
    return r;
}

__device__ __forceinline__ void mma_tf32(float& c0, float& c1, float& c2, float& c3,
                                         uint32_t a0, uint32_t a1, uint32_t a2, uint32_t a3,
                                         uint32_t b0, uint32_t b1) {
    asm volatile("mma.sync.aligned.m16n8k8.row.col.f32.tf32.tf32.f32 "
                 "{%0,%1,%2,%3},{%4,%5,%6,%7},{%8,%9},{%0,%1,%2,%3};"
                 : "+f"(c0), "+f"(c1), "+f"(c2), "+f"(c3)
                 : "r"(a0), "r"(a1), "r"(a2), "r"(a3), "r"(b0), "r"(b1));
}

// ---------------- setup kernels ----------------
__global__ void zero_kernel() {
    int i = blockIdx.x * 256 + threadIdx.x;
    if (i < 6 * NP) g_cnt[i] = 0;
}

__global__ void deg_kernel(const int* __restrict__ es, const int* __restrict__ ed) {
    int i = blockIdx.x * 256 + threadIdx.x;
    if (i >= RREL * NE) return;
    int r = i / NE;
    atomicAdd(&g_cnt[r * NP + es[i]], 1);
    atomicAdd(&g_cnt[3 * NP + r * NP + ed[i]], 1);
}

// ---- 3-kernel exclusive scan over dst counts ----
__global__ void scan_blocksum_kernel() {
    __shared__ int sm[SCAN_BLK];
    int i = blockIdx.x * SCAN_BLK + threadIdx.x;
    int v = (i < NDST) ? g_cnt[3 * NP + i] : 0;
    sm[threadIdx.x] = v;
    __syncthreads();
    for (int off = SCAN_BLK / 2; off > 0; off >>= 1) {
        if (threadIdx.x < off) sm[threadIdx.x] += sm[threadIdx.x + off];
        __syncthreads();
    }
    if (threadIdx.x == 0) g_bsum[blockIdx.x] = sm[0];
}

__global__ void scan_spine_kernel() {
    __shared__ int sm[1024];
    int t = threadIdx.x;
    int v = (t < SCAN_NB) ? g_bsum[t] : 0;
    sm[t] = v;
    __syncthreads();
    for (int off = 1; off < 1024; off <<= 1) {
        int add = (t >= off) ? sm[t - off] : 0;
        __syncthreads();
        sm[t] += add;
        __syncthreads();
    }
    if (t < SCAN_NB) g_bsum[t] = sm[t] - v;   // exclusive
}

__global__ void scan_apply_kernel() {
    __shared__ int sm[SCAN_BLK];
    int i = blockIdx.x * SCAN_BLK + threadIdx.x;
    int t = threadIdx.x;
    int v = (i < NDST) ? g_cnt[3 * NP + i] : 0;
    sm[t] = v;
    __syncthreads();
    for (int off = 1; off < SCAN_BLK; off <<= 1) {
        int add = (t >= off) ? sm[t - off] : 0;
        __syncthreads();
        sm[t] += add;
        __syncthreads();
    }
    if (i < NDST) {
        int excl = g_bsum[blockIdx.x] + sm[t] - v;
        g_rowptr[i] = excl;
        g_cursor[i] = excl;
        g_rs[i]          = rsqrtf(fmaxf((float)g_cnt[i], 1.0f));
        g_rs[3 * NP + i] = rsqrtf(fmaxf((float)v, 1.0f));
    }
    if (i == 0) g_rowptr[NDST] = RREL * NE;
}

__global__ void fill_csr_kernel(const int* __restrict__ es, const int* __restrict__ ed) {
    int i = blockIdx.x * 256 + threadIdx.x;
    if (i >= RREL * NE) return;
    int r = i / NE;
    int pos = atomicAdd(&g_cursor[r * NP + ed[i]], 1);
    g_csr[pos] = es[i];
}

// ---------------- layer-1 projection: tf32 tensor-core MMA ----------------
// Tile 128(M) x 64(N), K chunked x32. 8 warps, warp w owns rows [16w,16w+16).
// xs stride 36 (banks 4g+t4 distinct), Ws stride 72 (banks 8k+n distinct).
#define XS_STR 36
#define WS_STR 72
__global__ void __launch_bounds__(256) proj1_kernel(const float* __restrict__ x,
                                                    const float* __restrict__ W0) {
    __shared__ uint32_t xs[128 * XS_STR];   // tf32 bits, 18.4 KB
    __shared__ uint32_t Ws[32 * WS_STR];    // tf32 bits, 9.2 KB
    const int r = blockIdx.y, t = threadIdx.x, m0 = blockIdx.x * 128;
    const int lane = t & 31, w = t >> 5;
    const int g = lane >> 2, t4 = lane & 3;

    float c[8][4];
#pragma unroll
    for (int j = 0; j < 8; ++j)
#pragma unroll
        for (int q = 0; q < 4; ++q) c[j][q] = 0.f;

    const float4* x4 = (const float4*)x;
    const float* W = W0 + r * FIN * FH;
    const int rowA = (w * 16 + g) * XS_STR;

    for (int cch = 0; cch < 4; ++cch) {
        // stage x[:, cch*32 : +32] scaled, as tf32
#pragma unroll
        for (int it = 0; it < 4; ++it) {
            int idx = t + it * 256;
            int row = idx >> 3, q = idx & 7;
            int m = m0 + row;
            float4 v = make_float4(0.f, 0.f, 0.f, 0.f); float s = 0.f;
            if (m < NP) { v = x4[m * 32 + cch * 8 + q]; s = g_rs[r * NP + m]; }
            uint32_t* p = &xs[row * XS_STR + q * 4];
            p[0] = f2tf32(v.x * s); p[1] = f2tf32(v.y * s);
            p[2] = f2tf32(v.z * s); p[3] = f2tf32(v.w * s);
        }
        // stage W[cch*32 : +32, :] as tf32
#pragma unroll
        for (int i = t; i < 32 * 64; i += 256)
            Ws[(i >> 6) * WS_STR + (i & 63)] = f2tf32(W[cch * 2048 + i]);
        __syncthreads();

#pragma unroll
        for (int ks = 0; ks < 4; ++ks) {
            const int kc = ks * 8;
            uint32_t a0 = xs[rowA + kc + t4];
            uint32_t a1 = xs[rowA + 8 * XS_STR + kc + t4];
            uint32_t a2 = xs[rowA + kc + t4 + 4];
            uint32_t a3 = xs[rowA + 8 * XS_STR + kc + t4 + 4];
            const int kb = (kc + t4) * WS_STR + g;
#pragma unroll
            for (int j = 0; j < 8; ++j) {
                uint32_t b0 = Ws[kb + j * 8];
                uint32_t b1 = Ws[kb + 4 * WS_STR + j * 8];
                mma_tf32(c[j][0], c[j][1], c[j][2], c[j][3], a0, a1, a2, a3, b0, b1);
            }
        }
        __syncthreads();
    }

    // epilogue: c0,c1 -> (row0, col..col+1); c2,c3 -> (row0+8, ...)
    const int row0 = m0 + w * 16 + g;
    const int colb = t4 * 2;
#pragma unroll
    for (int j = 0; j < 8; ++j) {
        int col = j * 8 + colb;
        if (row0 < NP)
            *(float2*)&g_h[(r * NP + row0) * FH + col] = make_float2(c[j][0], c[j][1]);
        if (row0 + 8 < NP)
            *(float2*)&g_h[(r * NP + row0 + 8) * FH + col] = make_float2(c[j][2], c[j][3]);
    }
}

// ---------------- layer-1 gather (pull, CSR) — R5 best config ----------------
__global__ void __launch_bounds__(256) gather1_kernel(const float* __restrict__ b0) {
    int w = (blockIdx.x * 256 + threadIdx.x) >> 5;   // dst node
    int lane = threadIdx.x & 31;
    if (w >= NP) return;
    float a0 = 0.f, a1 = 0.f;
#pragma unroll
    for (int r = 0; r < RREL; ++r) {
        int beg = g_rowptr[r * NP + w];
        int end = g_rowptr[r * NP + w + 1];
        float sc = g_rs[3 * NP + r * NP + w];
        const float* hb = g_h + (size_t)r * NP * FH;
        float s0 = 0.f, s1 = 0.f;
        int e = beg;
        for (; e + 4 <= end; e += 4) {
            int i0 = g_csr[e], i1 = g_csr[e + 1], i2 = g_csr[e + 2], i3 = g_csr[e + 3];
            float v0a = hb[i0 * FH + lane], v0b = hb[i0 * FH + 32 + lane];
            float v1a = hb[i1 * FH + lane], v1b = hb[i1 * FH + 32 + lane];
            float v2a = hb[i2 * FH + lane], v2b = hb[i2 * FH + 32 + lane];
            float v3a = hb[i3 * FH + lane], v3b = hb[i3 * FH + 32 + lane];
            s0 += (v0a + v1a) + (v2a + v3a);
            s1 += (v0b + v1b) + (v2b + v3b);
        }
        for (; e < end; ++e) {
            int s = g_csr[e];
            s0 += hb[s * FH + lane];
            s1 += hb[s * FH + 32 + lane];
        }
        a0 = fmaf(sc, s0, a0);
        a1 = fmaf(sc, s1, a1);
    }
    float bs0 = b0[lane]      + b0[FH + lane]      + b0[2 * FH + lane];
    float bs1 = b0[32 + lane] + b0[FH + 32 + lane] + b0[2 * FH + 32 + lane];
    g_h1[w * FH + lane]      = fmaxf(a0 + bs0, 0.f);
    g_h1[w * FH + 32 + lane] = fmaxf(a1 + bs1, 0.f);
}

// ---------------- layer-2 projection: fp32 scalar (precision-sensitive path) ----------------
__global__ void __launch_bounds__(256) proj2_kernel(const float* __restrict__ Wmu,
                                                    const float* __restrict__ Wls) {
    __shared__ float xs2[128 * 65];
    __shared__ float Ws2[64 * 32];
    const int r = blockIdx.y, t = threadIdx.x, m0 = blockIdx.x * 128;
    const int lane = t & 31, wid = t >> 5;
    const int cg = wid & 3, rg = wid >> 2;
    const int c0 = cg * 8;

    for (int i = t; i < 64 * 16; i += 256) {
        int k = i >> 4, c = i & 15;
        Ws2[k * 32 + c]      = Wmu[r * 1024 + i];
        Ws2[k * 32 + 16 + c] = Wls[r * 1024 + i];
    }
    const float4* h4 = (const float4*)g_h1;
#pragma unroll
    for (int it = 0; it < 8; ++it) {
        int idx = t + it * 256;
        int row = idx >> 4, q = idx & 15;
        int m = m0 + row;
        float4 v = make_float4(0.f, 0.f, 0.f, 0.f); float s = 0.f;
        if (m < NP) { v = h4[m * 16 + q]; s = g_rs[r * NP + m]; }
        float* p = &xs2[row * 65 + q * 4];
        p[0] = v.x * s; p[1] = v.y * s; p[2] = v.z * s; p[3] = v.w * s;
    }
    __syncthreads();

    float4 acc[2][2];
#pragma unroll
    for (int j = 0; j < 2; ++j) {
        acc[j][0] = make_float4(0.f, 0.f, 0.f, 0.f);
        acc[j][1] = make_float4(0.f, 0.f, 0.f, 0.f);
    }

    for (int k = 0; k < 64; ++k) {
        float4 w0 = *(const float4*)&Ws2[k * 32 + c0];
        float4 w1 = *(const float4*)&Ws2[k * 32 + c0 + 4];
#pragma unroll
        for (int j = 0; j < 2; ++j) {
            float xv = xs2[(rg * 64 + j * 32 + lane) * 65 + k];
            acc[j][0].x = fmaf(xv, w0.x, acc[j][0].x);
            acc[j][0].y = fmaf(xv, w0.y, acc[j][0].y);
            acc[j][0].z = fmaf(xv, w0.z, acc[j][0].z);
            acc[j][0].w = fmaf(xv, w0.w, acc[j][0].w);
            acc[j][1].x = fmaf(xv, w1.x, acc[j][1].x);
            acc[j][1].y = fmaf(xv, w1.y, acc[j][1].y);
            acc[j][1].z = fmaf(xv, w1.z, acc[j][1].z);
            acc[j][1].w = fmaf(xv, w1.w, acc[j][1].w);
        }
    }
#pragma unroll
    for (int j = 0; j < 2; ++j) {
        int m = m0 + rg * 64 + j * 32 + lane;
        if (m >= NP) continue;
        float4* o = (float4*)&g_h[(r * NP + m) * 32 + c0];
        o[0] = acc[j][0]; o[1] = acc[j][1];
    }
}

// ---------------- layer-2 gather — fuses bias + VGAE reparameterization ----------------
__global__ void __launch_bounds__(256) gather2_kernel(const float* __restrict__ bmu,
                                                      const float* __restrict__ bls,
                                                      float* __restrict__ out) {
    int w = (blockIdx.x * 256 + threadIdx.x) >> 5;   // dst node
    int lane = threadIdx.x & 31;
    if (w >= NP) return;
    float acc = 0.f;
#pragma unroll
    for (int r = 0; r < RREL; ++r) {
        int beg = g_rowptr[r * NP + w];
        int end = g_rowptr[r * NP + w + 1];
        float sc = g_rs[3 * NP + r * NP + w];
        const float* hb = g_h + (size_t)r * NP * 32;
        float s0 = 0.f;
        int e = beg;
        for (; e + 4 <= end; e += 4) {
            int i0 = g_csr[e], i1 = g_csr[e + 1], i2 = g_csr[e + 2], i3 = g_csr[e + 3];
            s0 += (hb[i0 * 32 + lane] + hb[i1 * 32 + lane])
                + (hb[i2 * 32 + lane] + hb[i3 * 32 + lane]);
        }
        for (; e < end; ++e) s0 += hb[g_csr[e] * 32 + lane];
        acc = fmaf(sc, s0, acc);
    }
    float bias = (lane < 16)
        ? (bmu[lane] + bmu[16 + lane] + bmu[32 + lane])
        : (bls[lane - 16] + bls[lane] + bls[lane + 16]);
    float val = acc + bias;
    float ls  = __shfl_sync(0xffffffffu, val, (lane + 16) & 31);
    uint32_t o0, o1;
    threefry_0_42(0u, (uint32_t)(w * 16 + lane), o0, o1);
    if (lane < 16)
        out[1000000 + w * 16 + lane] = val + jax_normal(o0 ^ o1) * expf(ls);
}

__global__ void score_kernel(const int* __restrict__ ps, const int* __restrict__ pd,
                             const int* __restrict__ ns, const int* __restrict__ nd,
                             float* __restrict__ out) {
    int i = blockIdx.x * 256 + threadIdx.x;
    if (i >= 2 * EPC) return;
    int s, d;
    if (i < EPC) { s = ps[i]; d = pd[i]; }
    else         { s = ns[i - EPC]; d = nd[i - EPC]; }
    const float4* h4 = (const float4*)(out + 1000000);
    float acc = 0.f;
#pragma unroll
    for (int q = 0; q < 4; ++q) {
        float4 a = h4[s * 4 + q], b = h4[d * 4 + q];
        acc += a.x * b.x + a.y * b.y + a.z * b.z + a.w * b.w;
    }
    out[i] = acc;
}

// ---------------- launch ----------------
extern "C" void kernel_launch(void* const* d_in, const int* in_sizes, int n_in,
                              void* d_out, int out_size) {
    const float* x   = (const float*)d_in[0];
    const float* W0  = (const float*)d_in[1];
    const float* b0  = (const float*)d_in[2];
    const float* Wmu = (const float*)d_in[3];
    const float* bmu = (const float*)d_in[4];
    const float* Wls = (const float*)d_in[5];
    const float* bls = (const float*)d_in[6];
    const int*   es  = (const int*)d_in[7];
    const int*   ed  = (const int*)d_in[8];
    const int*   ps  = (const int*)d_in[9];
    const int*   pd  = (const int*)d_in[10];
    const int*   ns  = (const int*)d_in[11];
    const int*   nd  = (const int*)d_in[12];
    float* out = (float*)d_out;

    const int GBLK = (NP * 32 + 255) / 256;       // warp-per-node grids

    zero_kernel         <<<(6 * NP + 255) / 256, 256>>>();
    deg_kernel          <<<(RREL * NE + 255) / 256, 256>>>(es, ed);
    scan_blocksum_kernel<<<SCAN_NB, SCAN_BLK>>>();
    scan_spine_kernel   <<<1, 1024>>>();
    scan_apply_kernel   <<<SCAN_NB, SCAN_BLK>>>();
    fill_csr_kernel     <<<(RREL * NE + 255) / 256, 256>>>(es, ed);
    proj1_kernel        <<<dim3(MBLK, RREL), 256>>>(x, W0);
    gather1_kernel      <<<GBLK, 256>>>(b0);
    proj2_kernel        <<<dim3(MBLK, RREL), 256>>>(Wmu, Wls);
    gather2_kernel      <<<GBLK, 256>>>(bmu, bls, out);
    score_kernel        <<<(2 * EPC + 255) / 256, 256>>>(ps, pd, ns, nd, out);
}

// round 11
// speedup vs baseline: 1.2527x; 1.0580x over previous
#include <cuda_runtime.h>
#include <cstdint>

#define NP   100000
#define RREL 3
#define NE   1600000
#define EPC  500000
#define FIN  128
#define FH   64
#define NDST (RREL * NP)          // 300000 scanned rows
#define SCAN_BLK 512
#define SCAN_NB  ((NDST + SCAN_BLK - 1) / SCAN_BLK)   // 586
#define MBLK 782                  // ceil(NP/128)

// ---------------- device scratch (static, allocation-free) ----------------
__device__ int   g_cnt[6 * NP];          // [0:3N) src counts, [3N:6N) dst counts
__device__ float g_rs [6 * NP];          // rsqrt(max(count,1)) same layout
__device__ float g_h  [RREL * NP * FH];  // per-relation projected features (reused for layer 2)
__device__ float g_h1 [NP * FH];         // relu(hetero_conv1)
__device__ int   g_rowptr[NDST + 1];     // CSR row pointers (relations concatenated)
__device__ int   g_cursor[NDST];         // fill cursors
__device__ int   g_csr[RREL * NE];       // src node per in-edge, grouped by (rel,dst)
__device__ int   g_bsum[SCAN_NB];        // scan spine

// Threefry-2x32, 20 rounds, key = (0, 42)  (jax.random.key(42))
__device__ __forceinline__ void threefry_0_42(uint32_t x0, uint32_t x1,
                                              uint32_t& o0, uint32_t& o1) {
    const uint32_t k0 = 0u, k1 = 42u, k2 = 0x1BD11BDAu ^ 0u ^ 42u;
    x0 += k0; x1 += k1;
#define TF_RND(Rv) { x0 += x1; x1 = __funnelshift_l(x1, x1, (Rv)); x1 ^= x0; }
    TF_RND(13) TF_RND(15) TF_RND(26) TF_RND(6)   x0 += k1; x1 += k2 + 1u;
    TF_RND(17) TF_RND(29) TF_RND(16) TF_RND(24)  x0 += k2; x1 += k0 + 2u;
    TF_RND(13) TF_RND(15) TF_RND(26) TF_RND(6)   x0 += k0; x1 += k1 + 3u;
    TF_RND(17) TF_RND(29) TF_RND(16) TF_RND(24)  x0 += k1; x1 += k2 + 4u;
    TF_RND(13) TF_RND(15) TF_RND(26) TF_RND(6)   x0 += k2; x1 += k0 + 5u;
#undef TF_RND
    o0 = x0; o1 = x1;
}

// bits -> jax-style standard normal (uniform in [lo,1) then sqrt(2)*erfinv)
__device__ __forceinline__ float jax_normal(uint32_t bits) {
    const float LO = -0.99999994f;
    float f = __uint_as_float((bits >> 9) | 0x3f800000u) - 1.0f;
    float u = fmaxf(f * 2.0f + LO, LO);
    return 1.41421356237309515f * erfinvf(u);
}

__device__ __forceinline__ uint32_t f2tf32(float f) {
    uint32_t r;
    asm("cvt.rna.tf32.f32 %0, %1;" : "=r"(r) : "f"(f));
    return r;
}

__device__ __forceinline__ void mma_tf32(float& c0, float& c1, float& c2, float& c3,
                                         uint32_t a0, uint32_t a1, uint32_t a2, uint32_t a3,
                                         uint32_t b0, uint32_t b1) {
    asm volatile("mma.sync.aligned.m16n8k8.row.col.f32.tf32.tf32.f32 "
                 "{%0,%1,%2,%3},{%4,%5,%6,%7},{%8,%9},{%0,%1,%2,%3};"
                 : "+f"(c0), "+f"(c1), "+f"(c2), "+f"(c3)
                 : "r"(a0), "r"(a1), "r"(a2), "r"(a3), "r"(b0), "r"(b1));
}

// ---------------- setup kernels ----------------
__global__ void zero_kernel() {
    int i = blockIdx.x * 256 + threadIdx.x;
    if (i < 6 * NP) g_cnt[i] = 0;
}

__global__ void deg_kernel(const int* __restrict__ es, const int* __restrict__ ed) {
    int i = blockIdx.x * 256 + threadIdx.x;
    if (i >= RREL * NE) return;
    int r = i / NE;
    atomicAdd(&g_cnt[r * NP + es[i]], 1);
    atomicAdd(&g_cnt[3 * NP + r * NP + ed[i]], 1);
}

// ---- 3-kernel exclusive scan over dst counts ----
__global__ void scan_blocksum_kernel() {
    __shared__ int sm[SCAN_BLK];
    int i = blockIdx.x * SCAN_BLK + threadIdx.x;
    int v = (i < NDST) ? g_cnt[3 * NP + i] : 0;
    sm[threadIdx.x] = v;
    __syncthreads();
    for (int off = SCAN_BLK / 2; off > 0; off >>= 1) {
        if (threadIdx.x < off) sm[threadIdx.x] += sm[threadIdx.x + off];
        __syncthreads();
    }
    if (threadIdx.x == 0) g_bsum[blockIdx.x] = sm[0];
}

__global__ void scan_spine_kernel() {
    __shared__ int sm[1024];
    int t = threadIdx.x;
    int v = (t < SCAN_NB) ? g_bsum[t] : 0;
    sm[t] = v;
    __syncthreads();
    for (int off = 1; off < 1024; off <<= 1) {
        int add = (t >= off) ? sm[t - off] : 0;
        __syncthreads();
        sm[t] += add;
        __syncthreads();
    }
    if (t < SCAN_NB) g_bsum[t] = sm[t] - v;   // exclusive
}

__global__ void scan_apply_kernel() {
    __shared__ int sm[SCAN_BLK];
    int i = blockIdx.x * SCAN_BLK + threadIdx.x;
    int t = threadIdx.x;
    int v = (i < NDST) ? g_cnt[3 * NP + i] : 0;
    sm[t] = v;
    __syncthreads();
    for (int off = 1; off < SCAN_BLK; off <<= 1) {
        int add = (t >= off) ? sm[t - off] : 0;
        __syncthreads();
        sm[t] += add;
        __syncthreads();
    }
    if (i < NDST) {
        int excl = g_bsum[blockIdx.x] + sm[t] - v;
        g_rowptr[i] = excl;
        g_cursor[i] = excl;
        g_rs[i]          = rsqrtf(fmaxf((float)g_cnt[i], 1.0f));
        g_rs[3 * NP + i] = rsqrtf(fmaxf((float)v, 1.0f));
    }
    if (i == 0) g_rowptr[NDST] = RREL * NE;
}

__global__ void fill_csr_kernel(const int* __restrict__ es, const int* __restrict__ ed) {
    int i = blockIdx.x * 256 + threadIdx.x;
    if (i >= RREL * NE) return;
    int r = i / NE;
    int pos = atomicAdd(&g_cursor[r * NP + ed[i]], 1);
    g_csr[pos] = es[i];
}

// ---------------- layer-1 projection: tf32 tensor-core MMA ----------------
// Tile 128(M) x 64(N), K chunked x32. 8 warps, warp w owns rows [16w,16w+16).
#define XS_STR 36
#define WS_STR 72
__global__ void __launch_bounds__(256) proj1_kernel(const float* __restrict__ x,
                                                    const float* __restrict__ W0) {
    __shared__ uint32_t xs[128 * XS_STR];   // tf32 bits, 18.4 KB
    __shared__ uint32_t Ws[32 * WS_STR];    // tf32 bits, 9.2 KB
    const int r = blockIdx.y, t = threadIdx.x, m0 = blockIdx.x * 128;
    const int lane = t & 31, w = t >> 5;
    const int g = lane >> 2, t4 = lane & 3;

    float c[8][4];
#pragma unroll
    for (int j = 0; j < 8; ++j)
#pragma unroll
        for (int q = 0; q < 4; ++q) c[j][q] = 0.f;

    const float4* x4 = (const float4*)x;
    const float* W = W0 + r * FIN * FH;
    const int rowA = (w * 16 + g) * XS_STR;

    for (int cch = 0; cch < 4; ++cch) {
#pragma unroll
        for (int it = 0; it < 4; ++it) {
            int idx = t + it * 256;
            int row = idx >> 3, q = idx & 7;
            int m = m0 + row;
            float4 v = make_float4(0.f, 0.f, 0.f, 0.f); float s = 0.f;
            if (m < NP) { v = x4[m * 32 + cch * 8 + q]; s = g_rs[r * NP + m]; }
            uint32_t* p = &xs[row * XS_STR + q * 4];
            p[0] = f2tf32(v.x * s); p[1] = f2tf32(v.y * s);
            p[2] = f2tf32(v.z * s); p[3] = f2tf32(v.w * s);
        }
#pragma unroll
        for (int i = t; i < 32 * 64; i += 256)
            Ws[(i >> 6) * WS_STR + (i & 63)] = f2tf32(W[cch * 2048 + i]);
        __syncthreads();

#pragma unroll
        for (int ks = 0; ks < 4; ++ks) {
            const int kc = ks * 8;
            uint32_t a0 = xs[rowA + kc + t4];
            uint32_t a1 = xs[rowA + 8 * XS_STR + kc + t4];
            uint32_t a2 = xs[rowA + kc + t4 + 4];
            uint32_t a3 = xs[rowA + 8 * XS_STR + kc + t4 + 4];
            const int kb = (kc + t4) * WS_STR + g;
#pragma unroll
            for (int j = 0; j < 8; ++j) {
                uint32_t b0 = Ws[kb + j * 8];
                uint32_t b1 = Ws[kb + 4 * WS_STR + j * 8];
                mma_tf32(c[j][0], c[j][1], c[j][2], c[j][3], a0, a1, a2, a3, b0, b1);
            }
        }
        __syncthreads();
    }

    const int row0 = m0 + w * 16 + g;
    const int colb = t4 * 2;
#pragma unroll
    for (int j = 0; j < 8; ++j) {
        int col = j * 8 + colb;
        if (row0 < NP)
            *(float2*)&g_h[(r * NP + row0) * FH + col] = make_float2(c[j][0], c[j][1]);
        if (row0 + 8 < NP)
            *(float2*)&g_h[(r * NP + row0 + 8) * FH + col] = make_float2(c[j][2], c[j][3]);
    }
}

// ---------------- layer-1 gather (pull, CSR) — R5 best config ----------------
__global__ void __launch_bounds__(256) gather1_kernel(const float* __restrict__ b0) {
    int w = (blockIdx.x * 256 + threadIdx.x) >> 5;   // dst node
    int lane = threadIdx.x & 31;
    if (w >= NP) return;
    float a0 = 0.f, a1 = 0.f;
#pragma unroll
    for (int r = 0; r < RREL; ++r) {
        int beg = g_rowptr[r * NP + w];
        int end = g_rowptr[r * NP + w + 1];
        float sc = g_rs[3 * NP + r * NP + w];
        const float* hb = g_h + (size_t)r * NP * FH;
        float s0 = 0.f, s1 = 0.f;
        int e = beg;
        for (; e + 4 <= end; e += 4) {
            int i0 = g_csr[e], i1 = g_csr[e + 1], i2 = g_csr[e + 2], i3 = g_csr[e + 3];
            float v0a = hb[i0 * FH + lane], v0b = hb[i0 * FH + 32 + lane];
            float v1a = hb[i1 * FH + lane], v1b = hb[i1 * FH + 32 + lane];
            float v2a = hb[i2 * FH + lane], v2b = hb[i2 * FH + 32 + lane];
            float v3a = hb[i3 * FH + lane], v3b = hb[i3 * FH + 32 + lane];
            s0 += (v0a + v1a) + (v2a + v3a);
            s1 += (v0b + v1b) + (v2b + v3b);
        }
        for (; e < end; ++e) {
            int s = g_csr[e];
            s0 += hb[s * FH + lane];
            s1 += hb[s * FH + 32 + lane];
        }
        a0 = fmaf(sc, s0, a0);
        a1 = fmaf(sc, s1, a1);
    }
    float bs0 = b0[lane]      + b0[FH + lane]      + b0[2 * FH + lane];
    float bs1 = b0[32 + lane] + b0[FH + 32 + lane] + b0[2 * FH + 32 + lane];
    g_h1[w * FH + lane]      = fmaxf(a0 + bs0, 0.f);
    g_h1[w * FH + 32 + lane] = fmaxf(a1 + bs1, 0.f);
}

// ---------------- layer-2 projection: tf32 tensor-core MMA ----------------
// Tile 128(M) x 32(N), K=64 single chunk. 8 warps, warp w owns rows [16w,16w+16).
// Ws cols: [0:16) = W_mu, [16:32) = W_ls.
// xs stride 68 -> A-frag banks (4g+t4) distinct; Ws stride 40 -> B-frag banks (8t4+g) distinct.
#define X2_STR 68
#define W2_STR 40
__global__ void __launch_bounds__(256) proj2_kernel(const float* __restrict__ Wmu,
                                                    const float* __restrict__ Wls) {
    __shared__ uint32_t xs[128 * X2_STR];   // 34.8 KB
    __shared__ uint32_t Ws[64 * W2_STR];    // 10.2 KB
    const int r = blockIdx.y, t = threadIdx.x, m0 = blockIdx.x * 128;
    const int lane = t & 31, w = t >> 5;
    const int g = lane >> 2, t4 = lane & 3;

    // stage W: k=i>>4, c=i&15
    for (int i = t; i < 64 * 16; i += 256) {
        int k = i >> 4, c = i & 15;
        Ws[k * W2_STR + c]      = f2tf32(Wmu[r * 1024 + i]);
        Ws[k * W2_STR + 16 + c] = f2tf32(Wls[r * 1024 + i]);
    }
    // stage x = h1 scaled: 128 rows x 16 float4
    const float4* h4 = (const float4*)g_h1;
#pragma unroll
    for (int it = 0; it < 8; ++it) {
        int idx = t + it * 256;
        int row = idx >> 4, q = idx & 15;
        int m = m0 + row;
        float4 v = make_float4(0.f, 0.f, 0.f, 0.f); float s = 0.f;
        if (m < NP) { v = h4[m * 16 + q]; s = g_rs[r * NP + m]; }
        uint32_t* p = &xs[row * X2_STR + q * 4];
        p[0] = f2tf32(v.x * s); p[1] = f2tf32(v.y * s);
        p[2] = f2tf32(v.z * s); p[3] = f2tf32(v.w * s);
    }
    __syncthreads();

    float c[4][4];
#pragma unroll
    for (int j = 0; j < 4; ++j)
#pragma unroll
        for (int q = 0; q < 4; ++q) c[j][q] = 0.f;

    const int rowA = (w * 16 + g) * X2_STR;
#pragma unroll
    for (int ks = 0; ks < 8; ++ks) {
        const int kc = ks * 8;
        uint32_t a0 = xs[rowA + kc + t4];
        uint32_t a1 = xs[rowA + 8 * X2_STR + kc + t4];
        uint32_t a2 = xs[rowA + kc + t4 + 4];
        uint32_t a3 = xs[rowA + 8 * X2_STR + kc + t4 + 4];
        const int kb = (kc + t4) * W2_STR + g;
#pragma unroll
        for (int j = 0; j < 4; ++j) {
            uint32_t b0 = Ws[kb + j * 8];
            uint32_t b1 = Ws[kb + 4 * W2_STR + j * 8];
            mma_tf32(c[j][0], c[j][1], c[j][2], c[j][3], a0, a1, a2, a3, b0, b1);
        }
    }

    const int row0 = m0 + w * 16 + g;
    const int colb = t4 * 2;
#pragma unroll
    for (int j = 0; j < 4; ++j) {
        int col = j * 8 + colb;
        if (row0 < NP)
            *(float2*)&g_h[(r * NP + row0) * 32 + col] = make_float2(c[j][0], c[j][1]);
        if (row0 + 8 < NP)
            *(float2*)&g_h[(r * NP + row0 + 8) * 32 + col] = make_float2(c[j][2], c[j][3]);
    }
}

// ---------------- layer-2 gather — fuses bias + VGAE reparameterization ----------------
__global__ void __launch_bounds__(256) gather2_kernel(const float* __restrict__ bmu,
                                                      const float* __restrict__ bls,
                                                      float* __restrict__ out) {
    int w = (blockIdx.x * 256 + threadIdx.x) >> 5;   // dst node
    int lane = threadIdx.x & 31;
    if (w >= NP) return;
    float acc = 0.f;
#pragma unroll
    for (int r = 0; r < RREL; ++r) {
        int beg = g_rowptr[r * NP + w];
        int end = g_rowptr[r * NP + w + 1];
        float sc = g_rs[3 * NP + r * NP + w];
        const float* hb = g_h + (size_t)r * NP * 32;
        float s0 = 0.f;
        int e = beg;
        for (; e + 4 <= end; e += 4) {
            int i0 = g_csr[e], i1 = g_csr[e + 1], i2 = g_csr[e + 2], i3 = g_csr[e + 3];
            s0 += (hb[i0 * 32 + lane] + hb[i1 * 32 + lane])
                + (hb[i2 * 32 + lane] + hb[i3 * 32 + lane]);
        }
        for (; e < end; ++e) s0 += hb[g_csr[e] * 32 + lane];
        acc = fmaf(sc, s0, acc);
    }
    float bias = (lane < 16)
        ? (bmu[lane] + bmu[16 + lane] + bmu[32 + lane])
        : (bls[lane - 16] + bls[lane] + bls[lane + 16]);
    float val = acc + bias;
    float ls  = __shfl_sync(0xffffffffu, val, (lane + 16) & 31);
    uint32_t o0, o1;
    threefry_0_42(0u, (uint32_t)(w * 16 + lane), o0, o1);
    if (lane < 16)
        out[1000000 + w * 16 + lane] = val + jax_normal(o0 ^ o1) * expf(ls);
}

__global__ void score_kernel(const int* __restrict__ ps, const int* __restrict__ pd,
                             const int* __restrict__ ns, const int* __restrict__ nd,
                             float* __restrict__ out) {
    int i = blockIdx.x * 256 + threadIdx.x;
    if (i >= 2 * EPC) return;
    int s, d;
    if (i < EPC) { s = ps[i]; d = pd[i]; }
    else         { s = ns[i - EPC]; d = nd[i - EPC]; }
    const float4* h4 = (const float4*)(out + 1000000);
    float acc = 0.f;
#pragma unroll
    for (int q = 0; q < 4; ++q) {
        float4 a = h4[s * 4 + q], b = h4[d * 4 + q];
        acc += a.x * b.x + a.y * b.y + a.z * b.z + a.w * b.w;
    }
    out[i] = acc;
}

// ---------------- launch ----------------
extern "C" void kernel_launch(void* const* d_in, const int* in_sizes, int n_in,
                              void* d_out, int out_size) {
    const float* x   = (const float*)d_in[0];
    const float* W0  = (const float*)d_in[1];
    const float* b0  = (const float*)d_in[2];
    const float* Wmu = (const float*)d_in[3];
    const float* bmu = (const float*)d_in[4];
    const float* Wls = (const float*)d_in[5];
    const float* bls = (const float*)d_in[6];
    const int*   es  = (const int*)d_in[7];
    const int*   ed  = (const int*)d_in[8];
    const int*   ps  = (const int*)d_in[9];
    const int*   pd  = (const int*)d_in[10];
    const int*   ns  = (const int*)d_in[11];
    const int*   nd  = (const int*)d_in[12];
    float* out = (float*)d_out;

    const int GBLK = (NP * 32 + 255) / 256;       // warp-per-node grids

    zero_kernel         <<<(6 * NP + 255) / 256, 256>>>();
    deg_kernel          <<<(RREL * NE + 255) / 256, 256>>>(es, ed);
    scan_blocksum_kernel<<<SCAN_NB, SCAN_BLK>>>();
    scan_spine_kernel   <<<1, 1024>>>();
    scan_apply_kernel   <<<SCAN_NB, SCAN_BLK>>>();
    fill_csr_kernel     <<<(RREL * NE + 255) / 256, 256>>>(es, ed);
    proj1_kernel        <<<dim3(MBLK, RREL), 256>>>(x, W0);
    gather1_kernel      <<<GBLK, 256>>>(b0);
    proj2_kernel        <<<dim3(MBLK, RREL), 256>>>(Wmu, Wls);
    gather2_kernel      <<<GBLK, 256>>>(bmu, bls, out);
    score_kernel        <<<(2 * EPC + 255) / 256, 256>>>(ps, pd, ns, nd, out);
}

// round 13
// speedup vs baseline: 1.3597x; 1.0854x over previous
#include <cuda_runtime.h>
#include <cuda_fp16.h>
#include <cstdint>

#define NP   100000
#define RREL 3
#define NE   1600000
#define EPC  500000
#define FIN  128
#define FH   64
#define NDST (RREL * NP)          // 300000 scanned rows
#define SCAN_BLK 512
#define SCAN_NB  ((NDST + SCAN_BLK - 1) / SCAN_BLK)   // 586
#define MBLK 782                  // ceil(NP/128)

// ---------------- device scratch (static, allocation-free) ----------------
__device__ int    g_cnt[6 * NP];          // [0:3N) src counts, [3N:6N) dst counts
__device__ float  g_rs [6 * NP];          // rsqrt(max(count,1)) same layout
__device__ __half g_hh[RREL * NP * FH];   // per-relation projected features, fp16 (reused layer 2)
__device__ float  g_h1 [NP * FH];         // relu(hetero_conv1), fp32
__device__ int    g_rowptr[NDST + 1];     // CSR row pointers (relations concatenated)
__device__ int    g_cursor[NDST];         // fill cursors
__device__ int    g_csr[RREL * NE];       // src node per in-edge, grouped by (rel,dst)
__device__ int    g_bsum[SCAN_NB];        // scan spine

// Threefry-2x32, 20 rounds, key = (0, 42)  (jax.random.key(42))
__device__ __forceinline__ void threefry_0_42(uint32_t x0, uint32_t x1,
                                              uint32_t& o0, uint32_t& o1) {
    const uint32_t k0 = 0u, k1 = 42u, k2 = 0x1BD11BDAu ^ 0u ^ 42u;
    x0 += k0; x1 += k1;
#define TF_RND(Rv) { x0 += x1; x1 = __funnelshift_l(x1, x1, (Rv)); x1 ^= x0; }
    TF_RND(13) TF_RND(15) TF_RND(26) TF_RND(6)   x0 += k1; x1 += k2 + 1u;
    TF_RND(17) TF_RND(29) TF_RND(16) TF_RND(24)  x0 += k2; x1 += k0 + 2u;
    TF_RND(13) TF_RND(15) TF_RND(26) TF_RND(6)   x0 += k0; x1 += k1 + 3u;
    TF_RND(17) TF_RND(29) TF_RND(16) TF_RND(24)  x0 += k1; x1 += k2 + 4u;
    TF_RND(13) TF_RND(15) TF_RND(26) TF_RND(6)   x0 += k2; x1 += k0 + 5u;
#undef TF_RND
    o0 = x0; o1 = x1;
}

// bits -> jax-style standard normal (uniform in [lo,1) then sqrt(2)*erfinv)
__device__ __forceinline__ float jax_normal(uint32_t bits) {
    const float LO = -0.99999994f;
    float f = __uint_as_float((bits >> 9) | 0x3f800000u) - 1.0f;
    float u = fmaxf(f * 2.0f + LO, LO);
    return 1.41421356237309515f * erfinvf(u);
}

__device__ __forceinline__ uint32_t f2tf32(float f) {
    uint32_t r;
    asm("cvt.rna.tf32.f32 %0, %1;" : "=r"(r) : "f"(f));
    return r;
}

__device__ __forceinline__ void mma_tf32(float& c0, float& c1, float& c2, float& c3,
                                         uint32_t a0, uint32_t a1, uint32_t a2, uint32_t a3,
                                         uint32_t b0, uint32_t b1) {
    asm volatile("mma.sync.aligned.m16n8k8.row.col.f32.tf32.tf32.f32 "
                 "{%0,%1,%2,%3},{%4,%5,%6,%7},{%8,%9},{%0,%1,%2,%3};"
                 : "+f"(c0), "+f"(c1), "+f"(c2), "+f"(c3)
                 : "r"(a0), "r"(a1), "r"(a2), "r"(a3), "r"(b0), "r"(b1));
}

// ---------------- setup kernels ----------------
__global__ void zero_kernel() {
    int i = blockIdx.x * 256 + threadIdx.x;
    if (i < 6 * NP) g_cnt[i] = 0;
}

__global__ void deg_kernel(const int* __restrict__ es, const int* __restrict__ ed) {
    int i = blockIdx.x * 256 + threadIdx.x;
    if (i >= RREL * NE) return;
    int r = i / NE;
    atomicAdd(&g_cnt[r * NP + es[i]], 1);
    atomicAdd(&g_cnt[3 * NP + r * NP + ed[i]], 1);
}

// ---- 3-kernel exclusive scan over dst counts ----
__global__ void scan_blocksum_kernel() {
    __shared__ int sm[SCAN_BLK];
    int i = blockIdx.x * SCAN_BLK + threadIdx.x;
    int v = (i < NDST) ? g_cnt[3 * NP + i] : 0;
    sm[threadIdx.x] = v;
    __syncthreads();
    for (int off = SCAN_BLK / 2; off > 0; off >>= 1) {
        if (threadIdx.x < off) sm[threadIdx.x] += sm[threadIdx.x + off];
        __syncthreads();
    }
    if (threadIdx.x == 0) g_bsum[blockIdx.x] = sm[0];
}

__global__ void scan_spine_kernel() {
    __shared__ int sm[1024];
    int t = threadIdx.x;
    int v = (t < SCAN_NB) ? g_bsum[t] : 0;
    sm[t] = v;
    __syncthreads();
    for (int off = 1; off < 1024; off <<= 1) {
        int add = (t >= off) ? sm[t - off] : 0;
        __syncthreads();
        sm[t] += add;
        __syncthreads();
    }
    if (t < SCAN_NB) g_bsum[t] = sm[t] - v;   // exclusive
}

__global__ void scan_apply_kernel() {
    __shared__ int sm[SCAN_BLK];
    int i = blockIdx.x * SCAN_BLK + threadIdx.x;
    int t = threadIdx.x;
    int v = (i < NDST) ? g_cnt[3 * NP + i] : 0;
    sm[t] = v;
    __syncthreads();
    for (int off = 1; off < SCAN_BLK; off <<= 1) {
        int add = (t >= off) ? sm[t - off] : 0;
        __syncthreads();
        sm[t] += add;
        __syncthreads();
    }
    if (i < NDST) {
        int excl = g_bsum[blockIdx.x] + sm[t] - v;
        g_rowptr[i] = excl;
        g_cursor[i] = excl;
        g_rs[i]          = rsqrtf(fmaxf((float)g_cnt[i], 1.0f));
        g_rs[3 * NP + i] = rsqrtf(fmaxf((float)v, 1.0f));
    }
    if (i == 0) g_rowptr[NDST] = RREL * NE;
}

__global__ void fill_csr_kernel(const int* __restrict__ es, const int* __restrict__ ed) {
    int i = blockIdx.x * 256 + threadIdx.x;
    if (i >= RREL * NE) return;
    int r = i / NE;
    int pos = atomicAdd(&g_cursor[r * NP + ed[i]], 1);
    g_csr[pos] = es[i];
}

// ---------------- layer-1 projection: tf32 tensor-core MMA, fp16 output ----------------
// Tile 128(M) x 64(N), K chunked x32. 8 warps, warp w owns rows [16w,16w+16).
#define XS_STR 36
#define WS_STR 72
__global__ void __launch_bounds__(256) proj1_kernel(const float* __restrict__ x,
                                                    const float* __restrict__ W0) {
    __shared__ uint32_t xs[128 * XS_STR];   // tf32 bits, 18.4 KB
    __shared__ uint32_t Ws[32 * WS_STR];    // tf32 bits, 9.2 KB
    const int r = blockIdx.y, t = threadIdx.x, m0 = blockIdx.x * 128;
    const int lane = t & 31, w = t >> 5;
    const int g = lane >> 2, t4 = lane & 3;

    float c[8][4];
#pragma unroll
    for (int j = 0; j < 8; ++j)
#pragma unroll
        for (int q = 0; q < 4; ++q) c[j][q] = 0.f;

    const float4* x4 = (const float4*)x;
    const float* W = W0 + r * FIN * FH;
    const int rowA = (w * 16 + g) * XS_STR;

    for (int cch = 0; cch < 4; ++cch) {
#pragma unroll
        for (int it = 0; it < 4; ++it) {
            int idx = t + it * 256;
            int row = idx >> 3, q = idx & 7;
            int m = m0 + row;
            float4 v = make_float4(0.f, 0.f, 0.f, 0.f); float s = 0.f;
            if (m < NP) { v = x4[m * 32 + cch * 8 + q]; s = g_rs[r * NP + m]; }
            uint32_t* p = &xs[row * XS_STR + q * 4];
            p[0] = f2tf32(v.x * s); p[1] = f2tf32(v.y * s);
            p[2] = f2tf32(v.z * s); p[3] = f2tf32(v.w * s);
        }
#pragma unroll
        for (int i = t; i < 32 * 64; i += 256)
            Ws[(i >> 6) * WS_STR + (i & 63)] = f2tf32(W[cch * 2048 + i]);
        __syncthreads();

#pragma unroll
        for (int ks = 0; ks < 4; ++ks) {
            const int kc = ks * 8;
            uint32_t a0 = xs[rowA + kc + t4];
            uint32_t a1 = xs[rowA + 8 * XS_STR + kc + t4];
            uint32_t a2 = xs[rowA + kc + t4 + 4];
            uint32_t a3 = xs[rowA + 8 * XS_STR + kc + t4 + 4];
            const int kb = (kc + t4) * WS_STR + g;
#pragma unroll
            for (int j = 0; j < 8; ++j) {
                uint32_t b0 = Ws[kb + j * 8];
                uint32_t b1 = Ws[kb + 4 * WS_STR + j * 8];
                mma_tf32(c[j][0], c[j][1], c[j][2], c[j][3], a0, a1, a2, a3, b0, b1);
            }
        }
        __syncthreads();
    }

    // epilogue: adjacent col pairs -> half2; row = 32 half2
    __half2* oh = (__half2*)g_hh;
    const int row0 = m0 + w * 16 + g;
#pragma unroll
    for (int j = 0; j < 8; ++j) {
        int h2i = j * 4 + t4;                 // (j*8 + t4*2)/2
        if (row0 < NP)
            oh[(r * NP + row0) * 32 + h2i] = __floats2half2_rn(c[j][0], c[j][1]);
        if (row0 + 8 < NP)
            oh[(r * NP + row0 + 8) * 32 + h2i] = __floats2half2_rn(c[j][2], c[j][3]);
    }
}

// ---------------- layer-1 gather: lane = half2 (dims 2l, 2l+1); 128B/warp/edge ----------------
__global__ void __launch_bounds__(256) gather1_kernel(const float* __restrict__ b0) {
    int w = (blockIdx.x * 256 + threadIdx.x) >> 5;   // dst node
    int lane = threadIdx.x & 31;
    if (w >= NP) return;
    float a0 = 0.f, a1 = 0.f;
#pragma unroll
    for (int r = 0; r < RREL; ++r) {
        int beg = g_rowptr[r * NP + w];
        int end = g_rowptr[r * NP + w + 1];
        float sc = g_rs[3 * NP + r * NP + w];
        const __half2* hb = (const __half2*)(g_hh + (size_t)r * NP * FH);
        float s0 = 0.f, s1 = 0.f;
        int e = beg;
        for (; e + 4 <= end; e += 4) {
            int i0 = g_csr[e], i1 = g_csr[e + 1], i2 = g_csr[e + 2], i3 = g_csr[e + 3];
            float2 v0 = __half22float2(hb[i0 * 32 + lane]);
            float2 v1 = __half22float2(hb[i1 * 32 + lane]);
            float2 v2 = __half22float2(hb[i2 * 32 + lane]);
            float2 v3 = __half22float2(hb[i3 * 32 + lane]);
            s0 += (v0.x + v1.x) + (v2.x + v3.x);
            s1 += (v0.y + v1.y) + (v2.y + v3.y);
        }
        for (; e < end; ++e) {
            float2 v = __half22float2(hb[g_csr[e] * 32 + lane]);
            s0 += v.x; s1 += v.y;
        }
        a0 = fmaf(sc, s0, a0);
        a1 = fmaf(sc, s1, a1);
    }
    int f = 2 * lane;
    float o0 = fmaxf(a0 + b0[f]     + b0[FH + f]     + b0[2 * FH + f],     0.f);
    float o1 = fmaxf(a1 + b0[f + 1] + b0[FH + f + 1] + b0[2 * FH + f + 1], 0.f);
    *(float2*)&g_h1[w * FH + f] = make_float2(o0, o1);
}

// ---------------- layer-2 projection: tf32 MMA, fp16 output ----------------
// Tile 128(M) x 32(N), K=64. Ws cols: [0:16)=W_mu, [16:32)=W_ls.
#define X2_STR 68
#define W2_STR 40
__global__ void __launch_bounds__(256) proj2_kernel(const float* __restrict__ Wmu,
                                                    const float* __restrict__ Wls) {
    __shared__ uint32_t xs[128 * X2_STR];   // 34.8 KB
    __shared__ uint32_t Ws[64 * W2_STR];    // 10.2 KB
    const int r = blockIdx.y, t = threadIdx.x, m0 = blockIdx.x * 128;
    const int lane = t & 31, w = t >> 5;
    const int g = lane >> 2, t4 = lane & 3;

    for (int i = t; i < 64 * 16; i += 256) {
        int k = i >> 4, c = i & 15;
        Ws[k * W2_STR + c]      = f2tf32(Wmu[r * 1024 + i]);
        Ws[k * W2_STR + 16 + c] = f2tf32(Wls[r * 1024 + i]);
    }
    const float4* h4 = (const float4*)g_h1;
#pragma unroll
    for (int it = 0; it < 8; ++it) {
        int idx = t + it * 256;
        int row = idx >> 4, q = idx & 15;
        int m = m0 + row;
        float4 v = make_float4(0.f, 0.f, 0.f, 0.f); float s = 0.f;
        if (m < NP) { v = h4[m * 16 + q]; s = g_rs[r * NP + m]; }
        uint32_t* p = &xs[row * X2_STR + q * 4];
        p[0] = f2tf32(v.x * s); p[1] = f2tf32(v.y * s);
        p[2] = f2tf32(v.z * s); p[3] = f2tf32(v.w * s);
    }
    __syncthreads();

    float c[4][4];
#pragma unroll
    for (int j = 0; j < 4; ++j)
#pragma unroll
        for (int q = 0; q < 4; ++q) c[j][q] = 0.f;

    const int rowA = (w * 16 + g) * X2_STR;
#pragma unroll
    for (int ks = 0; ks < 8; ++ks) {
        const int kc = ks * 8;
        uint32_t a0 = xs[rowA + kc + t4];
        uint32_t a1 = xs[rowA + 8 * X2_STR + kc + t4];
        uint32_t a2 = xs[rowA + kc + t4 + 4];
        uint32_t a3 = xs[rowA + 8 * X2_STR + kc + t4 + 4];
        const int kb = (kc + t4) * W2_STR + g;
#pragma unroll
        for (int j = 0; j < 4; ++j) {
            uint32_t b0 = Ws[kb + j * 8];
            uint32_t b1 = Ws[kb + 4 * W2_STR + j * 8];
            mma_tf32(c[j][0], c[j][1], c[j][2], c[j][3], a0, a1, a2, a3, b0, b1);
        }
    }

    // epilogue: row = 16 half2
    __half2* oh = (__half2*)g_hh;
    const int row0 = m0 + w * 16 + g;
#pragma unroll
    for (int j = 0; j < 4; ++j) {
        int h2i = j * 4 + t4;
        if (row0 < NP)
            oh[(r * NP + row0) * 16 + h2i] = __floats2half2_rn(c[j][0], c[j][1]);
        if (row0 + 8 < NP)
            oh[(r * NP + row0 + 8) * 16 + h2i] = __floats2half2_rn(c[j][2], c[j][3]);
    }
}

// ---------------- layer-2 gather — fp16 rows (64B/edge), fused reparameterization ----------------
__global__ void __launch_bounds__(256) gather2_kernel(const float* __restrict__ bmu,
                                                      const float* __restrict__ bls,
                                                      float* __restrict__ out) {
    int w = (blockIdx.x * 256 + threadIdx.x) >> 5;   // dst node
    int lane = threadIdx.x & 31;
    if (w >= NP) return;
    float acc = 0.f;
#pragma unroll
    for (int r = 0; r < RREL; ++r) {
        int beg = g_rowptr[r * NP + w];
        int end = g_rowptr[r * NP + w + 1];
        float sc = g_rs[3 * NP + r * NP + w];
        const __half* hb = g_hh + (size_t)r * NP * 32;
        float s0 = 0.f;
        int e = beg;
        for (; e + 4 <= end; e += 4) {
            int i0 = g_csr[e], i1 = g_csr[e + 1], i2 = g_csr[e + 2], i3 = g_csr[e + 3];
            float v0 = __half2float(hb[i0 * 32 + lane]);
            float v1 = __half2float(hb[i1 * 32 + lane]);
            float v2 = __half2float(hb[i2 * 32 + lane]);
            float v3 = __half2float(hb[i3 * 32 + lane]);
            s0 += (v0 + v1) + (v2 + v3);
        }
        for (; e < end; ++e) s0 += __half2float(hb[g_csr[e] * 32 + lane]);
        acc = fmaf(sc, s0, acc);
    }
    // lanes 0..15: mean dims; lanes 16..31: log_std dims
    float bias = (lane < 16)
        ? (bmu[lane] + bmu[16 + lane] + bmu[32 + lane])
        : (bls[lane - 16] + bls[lane] + bls[lane + 16]);
    float val = acc + bias;
    float ls  = __shfl_sync(0xffffffffu, val, (lane + 16) & 31);
    uint32_t o0, o1;
    threefry_0_42(0u, (uint32_t)(w * 16 + lane), o0, o1);
    if (lane < 16)
        out[1000000 + w * 16 + lane] = val + jax_normal(o0 ^ o1) * expf(ls);
}

__global__ void score_kernel(const int* __restrict__ ps, const int* __restrict__ pd,
                             const int* __restrict__ ns, const int* __restrict__ nd,
                             float* __restrict__ out) {
    int i = blockIdx.x * 256 + threadIdx.x;
    if (i >= 2 * EPC) return;
    int s, d;
    if (i < EPC) { s = ps[i]; d = pd[i]; }
    else         { s = ns[i - EPC]; d = nd[i - EPC]; }
    const float4* h4 = (const float4*)(out + 1000000);
    float acc = 0.f;
#pragma unroll
    for (int q = 0; q < 4; ++q) {
        float4 a = h4[s * 4 + q], b = h4[d * 4 + q];
        acc += a.x * b.x + a.y * b.y + a.z * b.z + a.w * b.w;
    }
    out[i] = acc;
}

// ---------------- launch ----------------
extern "C" void kernel_launch(void* const* d_in, const int* in_sizes, int n_in,
                              void* d_out, int out_size) {
    const float* x   = (const float*)d_in[0];
    const float* W0  = (const float*)d_in[1];
    const float* b0  = (const float*)d_in[2];
    const float* Wmu = (const float*)d_in[3];
    const float* bmu = (const float*)d_in[4];
    const float* Wls = (const float*)d_in[5];
    const float* bls = (const float*)d_in[6];
    const int*   es  = (const int*)d_in[7];
    const int*   ed  = (const int*)d_in[8];
    const int*   ps  = (const int*)d_in[9];
    const int*   pd  = (const int*)d_in[10];
    const int*   ns  = (const int*)d_in[11];
    const int*   nd  = (const int*)d_in[12];
    float* out = (float*)d_out;

    const int GBLK = (NP * 32 + 255) / 256;       // warp-per-node grids

    zero_kernel         <<<(6 * NP + 255) / 256, 256>>>();
    deg_kernel          <<<(RREL * NE + 255) / 256, 256>>>(es, ed);
    scan_blocksum_kernel<<<SCAN_NB, SCAN_BLK>>>();
    scan_spine_kernel   <<<1, 1024>>>();
    scan_apply_kernel   <<<SCAN_NB, SCAN_BLK>>>();
    fill_csr_kernel     <<<(RREL * NE + 255) / 256, 256>>>(es, ed);
    proj1_kernel        <<<dim3(MBLK, RREL), 256>>>(x, W0);
    gather1_kernel      <<<GBLK, 256>>>(b0);
    proj2_kernel        <<<dim3(MBLK, RREL), 256>>>(Wmu, Wls);
    gather2_kernel      <<<GBLK, 256>>>(bmu, bls, out);
    score_kernel        <<<(2 * EPC + 255) / 256, 256>>>(ps, pd, ns, nd, out);
}